// round 1
// baseline (speedup 1.0000x reference)
#include <cuda_runtime.h>

// ---------------------------------------------------------------------------
// Actor_22625887715353: x[4096,2048] -> relu(x@w1+b1)[4096,2048]
//                       -> relu(h1@w2+b2)[4096,1024]
//                       -> 64 softmax heads (32x width-32 RSU + 32x width-8 LAY)
//                       -> interleaved [4096, 16*80] output
// Round 0: fp32 SIMT tiled GEMMs (128x128x16, 8x8/thread) + fused bias/relu,
// packed head-weight GEMM, warp-shuffle softmax + scatter.
// ---------------------------------------------------------------------------

constexpr int BSZ    = 4096;
constexpr int IN_DIM = 2048;
constexpr int HID    = 2048;
constexpr int H2     = 1024;
constexpr int NHC    = 1280;   // 32 heads * 32 (rsu) + 32 heads * 8 (lay)

// Scratch (no cudaMalloc allowed)
__device__ float g_h1[BSZ * HID];        // 32 MB
__device__ float g_h2[BSZ * H2];         // 16 MB
__device__ float g_logits[BSZ * NHC];    // 20 MB
__device__ float g_wpack[H2 * NHC];      //  5 MB
__device__ float g_bpack[NHC];

// ---------------------------------------------------------------------------
// Generic fp32 GEMM: C[M,N] = A[M,K] @ B[K,N] + bias, optional ReLU.
// Tile 128x128, K-step 16, 256 threads, 8x8 per thread (4+4 split fragments).
// All dims are multiples of the tile sizes for this problem (no bounds checks).
// ---------------------------------------------------------------------------
template <bool RELU>
__global__ __launch_bounds__(256) void gemm_bias_act(
    const float* __restrict__ A, const float* __restrict__ B,
    const float* __restrict__ bias, float* __restrict__ C,
    int M, int N, int K)
{
    __shared__ float As[16][132];   // transposed A tile, padded
    __shared__ float Bs[16][132];   // B tile, padded (keeps float4 16B-aligned: 132*4=528, 528%16==0)

    const int tid = threadIdx.x;
    const int tx  = tid & 15;       // 0..15 -> column fragment
    const int ty  = tid >> 4;       // 0..15 -> row fragment
    const int bm  = blockIdx.y * 128;
    const int bn  = blockIdx.x * 128;

    const float* Aptr = A + (size_t)bm * K;
    const float* Bptr = B + bn;

    float acc[8][8];
#pragma unroll
    for (int i = 0; i < 8; i++)
#pragma unroll
        for (int j = 0; j < 8; j++) acc[i][j] = 0.f;

    for (int k0 = 0; k0 < K; k0 += 16) {
        // Load A tile 128x16 (512 float4), store transposed
#pragma unroll
        for (int i = 0; i < 2; i++) {
            int idx = tid + i * 256;            // 0..511
            int r   = idx >> 2;                 // 0..127
            int c4  = idx & 3;                  // 0..3 (float4 within the 16-wide K slab)
            float4 v = *(const float4*)(Aptr + (size_t)r * K + k0 + c4 * 4);
            As[c4 * 4 + 0][r] = v.x;
            As[c4 * 4 + 1][r] = v.y;
            As[c4 * 4 + 2][r] = v.z;
            As[c4 * 4 + 3][r] = v.w;
        }
        // Load B tile 16x128 (512 float4)
#pragma unroll
        for (int i = 0; i < 2; i++) {
            int idx = tid + i * 256;
            int r   = idx >> 5;                 // 0..15
            int c4  = idx & 31;                 // 0..31
            *(float4*)&Bs[r][c4 * 4] =
                *(const float4*)(Bptr + (size_t)(k0 + r) * N + c4 * 4);
        }
        __syncthreads();

#pragma unroll
        for (int kk = 0; kk < 16; kk++) {
            float4 a0 = *(const float4*)&As[kk][ty * 4];
            float4 a1 = *(const float4*)&As[kk][64 + ty * 4];
            float4 b0 = *(const float4*)&Bs[kk][tx * 4];
            float4 b1 = *(const float4*)&Bs[kk][64 + tx * 4];
            float a[8] = {a0.x, a0.y, a0.z, a0.w, a1.x, a1.y, a1.z, a1.w};
            float b[8] = {b0.x, b0.y, b0.z, b0.w, b1.x, b1.y, b1.z, b1.w};
#pragma unroll
            for (int i = 0; i < 8; i++)
#pragma unroll
                for (int j = 0; j < 8; j++)
                    acc[i][j] = fmaf(a[i], b[j], acc[i][j]);
        }
        __syncthreads();
    }

    // Epilogue: bias (+ReLU), float4 stores
#pragma unroll
    for (int i = 0; i < 8; i++) {
        int r = bm + ((i < 4) ? (ty * 4 + i) : (64 + ty * 4 + (i - 4)));
#pragma unroll
        for (int jh = 0; jh < 2; jh++) {
            int c = bn + jh * 64 + tx * 4;
            float4 v;
            v.x = acc[i][jh * 4 + 0] + bias[c + 0];
            v.y = acc[i][jh * 4 + 1] + bias[c + 1];
            v.z = acc[i][jh * 4 + 2] + bias[c + 2];
            v.w = acc[i][jh * 4 + 3] + bias[c + 3];
            if (RELU) {
                v.x = fmaxf(v.x, 0.f);
                v.y = fmaxf(v.y, 0.f);
                v.z = fmaxf(v.z, 0.f);
                v.w = fmaxf(v.w, 0.f);
            }
            *(float4*)(C + (size_t)r * N + c) = v;
        }
    }
}

// ---------------------------------------------------------------------------
// Pack head weights [32,1024,32] + [32,1024,8] into one K-major [1024,1280]
// matrix (column = head-major), and biases into [1280].
// ---------------------------------------------------------------------------
__global__ void pack_heads(const float* __restrict__ wr, const float* __restrict__ br,
                           const float* __restrict__ wl, const float* __restrict__ bl)
{
    int idx = blockIdx.x * blockDim.x + threadIdx.x;
    if (idx < H2 * NHC) {
        int h = idx / NHC;
        int c = idx % NHC;
        float v;
        if (c < 1024) {                       // rsu: col = k*32 + r
            int k = c >> 5, r = c & 31;
            v = wr[((size_t)k * H2 + h) * 32 + r];
        } else {                              // lay: col = 1024 + k*8 + l
            int cc = c - 1024;
            int k = cc >> 3, l = cc & 7;
            v = wl[((size_t)k * H2 + h) * 8 + l];
        }
        g_wpack[idx] = v;
    }
    if (idx < NHC)
        g_bpack[idx] = (idx < 1024) ? br[idx] : bl[idx - 1024];
}

// ---------------------------------------------------------------------------
// Per-row softmax over 64 head groups + scatter into interleaved output.
// Block = one batch row, 256 threads.
//   rsu head k (width 32): out col = (k/2)*80 + (k%2)*32 + r
//   lay head k (width 8):  out col = (k/2)*80 + 64 + (k%2)*8 + l
// ---------------------------------------------------------------------------
__global__ __launch_bounds__(256) void softmax_scatter(
    const float* __restrict__ logits, float* __restrict__ out)
{
    const int b   = blockIdx.x;
    const int tid = threadIdx.x;
    const float* row = logits + (size_t)b * NHC;
    float* orow      = out    + (size_t)b * NHC;

    // --- RSU heads: 8 warps x 4 iterations, warp-wide (32) softmax
    const int lane = tid & 31;
    const int warp = tid >> 5;
#pragma unroll
    for (int it = 0; it < 4; it++) {
        int k = warp + it * 8;                // head 0..31
        float v = row[k * 32 + lane];
        float m = v;
#pragma unroll
        for (int o = 16; o; o >>= 1) m = fmaxf(m, __shfl_xor_sync(0xffffffffu, m, o));
        float e = __expf(v - m);
        float s = e;
#pragma unroll
        for (int o = 16; o; o >>= 1) s += __shfl_xor_sync(0xffffffffu, s, o);
        orow[(k >> 1) * 80 + (k & 1) * 32 + lane] = e / s;
    }

    // --- LAY heads: 32 groups of 8 lanes, segmented shuffle softmax
    {
        int g  = tid >> 3;                    // head 0..31
        int l8 = tid & 7;
        float v = row[1024 + g * 8 + l8];
        float m = v;
#pragma unroll
        for (int o = 4; o; o >>= 1) m = fmaxf(m, __shfl_xor_sync(0xffffffffu, m, o));
        float e = __expf(v - m);
        float s = e;
#pragma unroll
        for (int o = 4; o; o >>= 1) s += __shfl_xor_sync(0xffffffffu, s, o);
        orow[(g >> 1) * 80 + 64 + (g & 1) * 8 + l8] = e / s;
    }
}

// ---------------------------------------------------------------------------
extern "C" void kernel_launch(void* const* d_in, const int* in_sizes, int n_in,
                              void* d_out, int out_size)
{
    const float* x  = (const float*)d_in[0];
    const float* w1 = (const float*)d_in[1];
    const float* b1 = (const float*)d_in[2];
    const float* w2 = (const float*)d_in[3];
    const float* b2 = (const float*)d_in[4];
    const float* wr = (const float*)d_in[5];
    const float* br = (const float*)d_in[6];
    const float* wl = (const float*)d_in[7];
    const float* bl = (const float*)d_in[8];
    float* out = (float*)d_out;

    float *h1, *h2, *lg, *wp, *bp;
    cudaGetSymbolAddress((void**)&h1, g_h1);
    cudaGetSymbolAddress((void**)&h2, g_h2);
    cudaGetSymbolAddress((void**)&lg, g_logits);
    cudaGetSymbolAddress((void**)&wp, g_wpack);
    cudaGetSymbolAddress((void**)&bp, g_bpack);

    // Pack head weights (independent of GEMM1/2 but cheap; run first)
    pack_heads<<<(H2 * NHC + 255) / 256, 256>>>(wr, br, wl, bl);

    // h1 = relu(x @ w1 + b1)          [4096,2048] x [2048,2048]
    {
        dim3 grid(HID / 128, BSZ / 128);
        gemm_bias_act<true><<<grid, 256>>>(x, w1, b1, h1, BSZ, HID, IN_DIM);
    }
    // h2 = relu(h1 @ w2 + b2)         [4096,2048] x [2048,1024]
    {
        dim3 grid(H2 / 128, BSZ / 128);
        gemm_bias_act<true><<<grid, 256>>>(h1, w2, b2, h2, BSZ, H2, HID);
    }
    // logits = h2 @ wpack + bpack     [4096,1024] x [1024,1280]
    {
        dim3 grid(NHC / 128, BSZ / 128);
        gemm_bias_act<false><<<grid, 256>>>(h2, wp, bp, lg, BSZ, NHC, H2);
    }
    // softmax per head + interleaved scatter
    softmax_scatter<<<BSZ, 256>>>(lg, out);
}

// round 3
// speedup vs baseline: 2.3238x; 2.3238x over previous
#include <cuda_runtime.h>
#include <cuda_bf16.h>
#include <cstdint>

// ---------------------------------------------------------------------------
// Actor_22625887715353 — round 3: mma.sync (HMMA) bf16x3 split-precision GEMMs.
// Toolchain targets plain sm_100 => tcgen05/TMEM unavailable; use family-
// agnostic tensor path: mma.sync.m16n8k16 + ldmatrix + cp.async pipeline.
//   h1 = relu(x@w1+b1); h2 = relu(h1@w2+b2); logits = h2@Wpack+bpack;
//   per-head softmax + interleaved scatter.
// Each GEMM: D = Ah*Bh + Ah*Bl + Al*Bh (bf16 frags, fp32 accum).
// ---------------------------------------------------------------------------

constexpr int BSZ = 4096, IN_DIM = 2048, HID = 2048, H2 = 1024, NHC = 1280;

// ---- device scratch (no cudaMalloc allowed) ----
__device__ __nv_bfloat16 g_xh[BSZ * IN_DIM], g_xl[BSZ * IN_DIM];
__device__ __nv_bfloat16 g_w1h[HID * IN_DIM], g_w1l[HID * IN_DIM];   // [N=2048,K=2048]
__device__ __nv_bfloat16 g_w2h[H2 * HID],   g_w2l[H2 * HID];         // [N=1024,K=2048]
__device__ __nv_bfloat16 g_wph[NHC * H2],   g_wpl[NHC * H2];         // [N=1280,K=1024]
__device__ __nv_bfloat16 g_h1h[BSZ * HID],  g_h1l[BSZ * HID];
__device__ __nv_bfloat16 g_h2h[BSZ * H2],   g_h2l[BSZ * H2];
__device__ float g_logits[BSZ * NHC];
__device__ float g_bpack[NHC];

// ===========================================================================
// Low-level helpers (all family-agnostic: sm_80+ ISA)
// ===========================================================================
__device__ __forceinline__ uint32_t cvta_s(const void* p) {
    uint32_t a;
    asm("{ .reg .u64 t; cvta.to.shared.u64 t, %1; cvt.u32.u64 %0, t; }" : "=r"(a) : "l"(p));
    return a;
}
#define CP16(d, s) asm volatile("cp.async.cg.shared.global [%0], [%1], 16;" :: "r"(d), "l"(s))
#define CP_COMMIT  asm volatile("cp.async.commit_group;")
#define CP_WAIT2   asm volatile("cp.async.wait_group 2;")
#define LDSM4(r0, r1, r2, r3, a) \
    asm volatile("ldmatrix.sync.aligned.m8n8.x4.shared.b16 {%0,%1,%2,%3}, [%4];" \
                 : "=r"(r0), "=r"(r1), "=r"(r2), "=r"(r3) : "r"(a))
#define MMA_BF16(d, a, b) \
    asm volatile("mma.sync.aligned.m16n8k16.row.col.f32.bf16.bf16.f32 " \
                 "{%0,%1,%2,%3},{%4,%5,%6,%7},{%8,%9},{%0,%1,%2,%3};" \
                 : "+f"((d)[0]), "+f"((d)[1]), "+f"((d)[2]), "+f"((d)[3]) \
                 : "r"((a)[0]), "r"((a)[1]), "r"((a)[2]), "r"((a)[3]), \
                   "r"((b)[0]), "r"((b)[1]))

// ===========================================================================
// GEMM: D[M,N] = A[M,K] @ B[N,K]^T (bf16x3) + bias, optional relu,
// output split bf16 hi/lo (SPLIT) or fp32 (!SPLIT).
// CTA 128x128, K-step 32, 256 thr (8 warps = 4M x 2N, warp tile 32x64),
// 4-stage cp.async pipeline.
// Smem tile layout: row-major [128 rows][32 bf16] = 64B/row; 16B chunk c of
// row r stored at chunk (c ^ ((r>>1)&3)) -> conflict-free ldmatrix + writes.
// ===========================================================================
constexpr int BM = 128, BN = 128, BK = 32, STAGES = 4;
constexpr int TB  = BM * 64;         // one tile: 8 KB
constexpr int STB = 4 * TB;          // stage (Ah,Al,Bh,Bl): 32 KB
constexpr int GEMM_SMEM = STAGES * STB;   // 128 KB

template <bool RELU, bool SPLIT>
__global__ __launch_bounds__(256, 1) void gemm_mma(
    const __nv_bfloat16* __restrict__ Ah, const __nv_bfloat16* __restrict__ Al,
    const __nv_bfloat16* __restrict__ Bh, const __nv_bfloat16* __restrict__ Bl,
    const float* __restrict__ bias,
    __nv_bfloat16* __restrict__ oh, __nv_bfloat16* __restrict__ ol,
    float* __restrict__ of, int M, int N, int K)
{
    extern __shared__ char smem[];
    const uint32_t sb = cvta_s(smem);
    const int tid = threadIdx.x, lane = tid & 31, warp = tid >> 5;
    const int bm = blockIdx.y * BM, bn = blockIdx.x * BN;
    const int m0w = (warp >> 1) * 32, n0w = (warp & 1) * 64;

    // ---- cp.async mapping: thread t loads chunk (t&3) of rows (t>>2), (t>>2)+64
    const int lr = tid >> 2, lc = tid & 3;
    const __nv_bfloat16* gp[4] = {Ah, Al, Bh, Bl};
    const int gr0[4] = {bm, bm, bn, bn};

    auto load_stage = [&](int s, int kc) {
        const uint32_t stb = sb + s * STB;
        const int kg = kc * BK + lc * 8;      // global k of this 16B chunk
#pragma unroll
        for (int t = 0; t < 4; t++) {
#pragma unroll
            for (int h = 0; h < 2; h++) {
                const int r = lr + h * 64;
                const uint32_t d = stb + t * TB + r * 64 + ((lc ^ ((r >> 1) & 3)) << 4);
                const void* g = gp[t] + (size_t)(gr0[t] + r) * K + kg;
                CP16(d, g);
            }
        }
    };

    float acc[2][8][4];
#pragma unroll
    for (int a = 0; a < 2; a++)
#pragma unroll
        for (int b = 0; b < 8; b++)
#pragma unroll
            for (int c = 0; c < 4; c++) acc[a][b][c] = 0.f;

    const int NS = K / BK;           // >= 32 for all three GEMMs
    load_stage(0, 0); CP_COMMIT;
    load_stage(1, 1); CP_COMMIT;
    load_stage(2, 2); CP_COMMIT;

    // ldmatrix lane geometry
    const int rA = lane & 15;                         // row within 16-row mfrag
    const int hA = lane >> 4;                         // k half (0/8)
    const int rB = (lane & 7) + ((lane >> 4) << 3);   // row within 16-row nfrag pair
    const int hB = (lane >> 3) & 1;                   // k half

    for (int i = 0; i < NS; i++) {
        CP_WAIT2;
        __syncthreads();                 // stage i visible to all; slot (i+3)&3 free
        if (i + 3 < NS) load_stage((i + 3) & 3, i + 3);
        CP_COMMIT;                       // commit every iter (possibly empty group)

        const uint32_t stb = sb + (i & 3) * STB;
#pragma unroll
        for (int ks = 0; ks < 2; ks++) {
            uint32_t ahf[2][4], alf[2][4], bhf[8][2], blf[8][2];
#pragma unroll
            for (int mf = 0; mf < 2; mf++) {
                const int r = m0w + mf * 16 + rA;
                const uint32_t off = r * 64 + (((ks * 2 + hA) ^ ((r >> 1) & 3)) << 4);
                LDSM4(ahf[mf][0], ahf[mf][1], ahf[mf][2], ahf[mf][3], stb + 0 * TB + off);
                LDSM4(alf[mf][0], alf[mf][1], alf[mf][2], alf[mf][3], stb + 1 * TB + off);
            }
#pragma unroll
            for (int p = 0; p < 4; p++) {
                const int r = n0w + p * 16 + rB;
                const uint32_t off = r * 64 + (((ks * 2 + hB) ^ ((r >> 1) & 3)) << 4);
                uint32_t q0, q1, q2, q3;
                LDSM4(q0, q1, q2, q3, stb + 2 * TB + off);
                bhf[2 * p][0] = q0; bhf[2 * p][1] = q1;
                bhf[2 * p + 1][0] = q2; bhf[2 * p + 1][1] = q3;
                LDSM4(q0, q1, q2, q3, stb + 3 * TB + off);
                blf[2 * p][0] = q0; blf[2 * p][1] = q1;
                blf[2 * p + 1][0] = q2; blf[2 * p + 1][1] = q3;
            }
#pragma unroll
            for (int mf = 0; mf < 2; mf++)
#pragma unroll
                for (int nf = 0; nf < 8; nf++) {
                    MMA_BF16(acc[mf][nf], ahf[mf], bhf[nf]);
                    MMA_BF16(acc[mf][nf], ahf[mf], blf[nf]);
                    MMA_BF16(acc[mf][nf], alf[mf], bhf[nf]);
                }
        }
    }

    // ---- epilogue: bias (+relu), split bf16 hi/lo or fp32 ----
#pragma unroll
    for (int mf = 0; mf < 2; mf++)
#pragma unroll
        for (int nf = 0; nf < 8; nf++) {
            const int col = bn + n0w + nf * 8 + (lane & 3) * 2;
            const float bx = __ldg(bias + col), by = __ldg(bias + col + 1);
#pragma unroll
            for (int h = 0; h < 2; h++) {
                const int row = bm + m0w + mf * 16 + (lane >> 2) + h * 8;
                float v0 = acc[mf][nf][2 * h]     + bx;
                float v1 = acc[mf][nf][2 * h + 1] + by;
                if (RELU) { v0 = fmaxf(v0, 0.f); v1 = fmaxf(v1, 0.f); }
                if (SPLIT) {
                    __nv_bfloat162 ph, pl;
                    ph.x = __float2bfloat16(v0); ph.y = __float2bfloat16(v1);
                    pl.x = __float2bfloat16(v0 - __bfloat162float(ph.x));
                    pl.y = __float2bfloat16(v1 - __bfloat162float(ph.y));
                    *(__nv_bfloat162*)(oh + (size_t)row * N + col) = ph;
                    *(__nv_bfloat162*)(ol + (size_t)row * N + col) = pl;
                } else {
                    *(float2*)(of + (size_t)row * N + col) = make_float2(v0, v1);
                }
            }
        }
}

// ===========================================================================
// Conversion kernels
// ===========================================================================
__global__ void split_fp32(const float* __restrict__ in, __nv_bfloat16* __restrict__ oh,
                           __nv_bfloat16* __restrict__ ol, int n)
{
    int i = (blockIdx.x * blockDim.x + threadIdx.x) * 4;
    if (i >= n) return;
    float4 v = *(const float4*)(in + i);
    float vv[4] = {v.x, v.y, v.z, v.w};
    __nv_bfloat16 h[4], l[4];
#pragma unroll
    for (int j = 0; j < 4; j++) {
        h[j] = __float2bfloat16(vv[j]);
        l[j] = __float2bfloat16(vv[j] - __bfloat162float(h[j]));
    }
    __nv_bfloat162 h01, h23, l01, l23;
    h01.x = h[0]; h01.y = h[1]; h23.x = h[2]; h23.y = h[3];
    l01.x = l[0]; l01.y = l[1]; l23.x = l[2]; l23.y = l[3];
    *(__nv_bfloat162*)(oh + i)     = h01;
    *(__nv_bfloat162*)(oh + i + 2) = h23;
    *(__nv_bfloat162*)(ol + i)     = l01;
    *(__nv_bfloat162*)(ol + i + 2) = l23;
}

// in: [R, C] fp32 -> out: [C, R] bf16 hi/lo  (weights -> [N rows, K cols])
__global__ void transpose_split(const float* __restrict__ in, __nv_bfloat16* __restrict__ oh,
                                __nv_bfloat16* __restrict__ ol, int R, int C)
{
    __shared__ float t[32][33];
    const int c0 = blockIdx.x * 32, r0 = blockIdx.y * 32;
    const int tx = threadIdx.x, ty = threadIdx.y;
#pragma unroll
    for (int k = 0; k < 4; k++)
        t[ty + 8 * k][tx] = in[(size_t)(r0 + ty + 8 * k) * C + c0 + tx];
    __syncthreads();
#pragma unroll
    for (int k = 0; k < 4; k++) {
        float v = t[tx][ty + 8 * k];
        __nv_bfloat16 h = __float2bfloat16(v);
        size_t o = (size_t)(c0 + ty + 8 * k) * R + r0 + tx;
        oh[o] = h;
        ol[o] = __float2bfloat16(v - __bfloat162float(h));
    }
}

// Pack head weights into [NHC=1280 rows (N), H2=1024 cols (K)] bf16 hi/lo + bias.
__global__ void pack_heads_t(const float* __restrict__ wr, const float* __restrict__ br,
                             const float* __restrict__ wl, const float* __restrict__ bl)
{
    int idx = blockIdx.x * blockDim.x + threadIdx.x;
    if (idx < NHC * H2) {
        int c = idx / H2, h = idx % H2;
        float v;
        if (c < 1024) { int k = c >> 5, r = c & 31; v = wr[((size_t)k * H2 + h) * 32 + r]; }
        else { int cc = c - 1024; int k = cc >> 3, l = cc & 7; v = wl[((size_t)k * H2 + h) * 8 + l]; }
        __nv_bfloat16 hi = __float2bfloat16(v);
        g_wph[idx] = hi;
        g_wpl[idx] = __float2bfloat16(v - __bfloat162float(hi));
    }
    if (idx < NHC) g_bpack[idx] = (idx < 1024) ? br[idx] : bl[idx - 1024];
}

// ===========================================================================
// Softmax per head + interleaved scatter
// ===========================================================================
__global__ __launch_bounds__(256) void softmax_scatter(
    const float* __restrict__ logits, float* __restrict__ out)
{
    const int b = blockIdx.x, tid = threadIdx.x;
    const float* row = logits + (size_t)b * NHC;
    float* orow = out + (size_t)b * NHC;
    const int lane = tid & 31, warp = tid >> 5;
#pragma unroll
    for (int it = 0; it < 4; it++) {
        int k = warp + it * 8;
        float v = row[k * 32 + lane];
        float m = v;
#pragma unroll
        for (int o = 16; o; o >>= 1) m = fmaxf(m, __shfl_xor_sync(0xffffffffu, m, o));
        float e = __expf(v - m);
        float s = e;
#pragma unroll
        for (int o = 16; o; o >>= 1) s += __shfl_xor_sync(0xffffffffu, s, o);
        orow[(k >> 1) * 80 + (k & 1) * 32 + lane] = e / s;
    }
    {
        int g = tid >> 3, l8 = tid & 7;
        float v = row[1024 + g * 8 + l8];
        float m = v;
#pragma unroll
        for (int o = 4; o; o >>= 1) m = fmaxf(m, __shfl_xor_sync(0xffffffffu, m, o));
        float e = __expf(v - m);
        float s = e;
#pragma unroll
        for (int o = 4; o; o >>= 1) s += __shfl_xor_sync(0xffffffffu, s, o);
        orow[(g >> 1) * 80 + 64 + (g & 1) * 8 + l8] = e / s;
    }
}

// ===========================================================================
// Host side
// ===========================================================================
extern "C" void kernel_launch(void* const* d_in, const int* in_sizes, int n_in,
                              void* d_out, int out_size)
{
    const float* x  = (const float*)d_in[0];
    const float* w1 = (const float*)d_in[1];
    const float* b1 = (const float*)d_in[2];
    const float* w2 = (const float*)d_in[3];
    const float* b2 = (const float*)d_in[4];
    const float* wr = (const float*)d_in[5];
    const float* br = (const float*)d_in[6];
    const float* wl = (const float*)d_in[7];
    const float* bl = (const float*)d_in[8];
    float* out = (float*)d_out;

    void *xh, *xl, *w1h, *w1l, *w2h, *w2l, *wph, *wpl, *h1h, *h1l, *h2h, *h2l, *lg, *bp;
    cudaGetSymbolAddress(&xh, g_xh);   cudaGetSymbolAddress(&xl, g_xl);
    cudaGetSymbolAddress(&w1h, g_w1h); cudaGetSymbolAddress(&w1l, g_w1l);
    cudaGetSymbolAddress(&w2h, g_w2h); cudaGetSymbolAddress(&w2l, g_w2l);
    cudaGetSymbolAddress(&wph, g_wph); cudaGetSymbolAddress(&wpl, g_wpl);
    cudaGetSymbolAddress(&h1h, g_h1h); cudaGetSymbolAddress(&h1l, g_h1l);
    cudaGetSymbolAddress(&h2h, g_h2h); cudaGetSymbolAddress(&h2l, g_h2l);
    cudaGetSymbolAddress(&lg, g_logits); cudaGetSymbolAddress(&bp, g_bpack);

    cudaFuncSetAttribute(gemm_mma<true, true>,
                         cudaFuncAttributeMaxDynamicSharedMemorySize, GEMM_SMEM);
    cudaFuncSetAttribute(gemm_mma<false, false>,
                         cudaFuncAttributeMaxDynamicSharedMemorySize, GEMM_SMEM);

    // conversions
    split_fp32<<<(BSZ * IN_DIM / 4 + 255) / 256, 256>>>(
        x, (__nv_bfloat16*)xh, (__nv_bfloat16*)xl, BSZ * IN_DIM);
    transpose_split<<<dim3(HID / 32, IN_DIM / 32), dim3(32, 8)>>>(
        w1, (__nv_bfloat16*)w1h, (__nv_bfloat16*)w1l, IN_DIM, HID);
    transpose_split<<<dim3(H2 / 32, HID / 32), dim3(32, 8)>>>(
        w2, (__nv_bfloat16*)w2h, (__nv_bfloat16*)w2l, HID, H2);
    pack_heads_t<<<(NHC * H2 + 255) / 256, 256>>>(wr, br, wl, bl);

    // GEMM1: h1 = relu(x@w1+b1)   [4096,2048] K=2048
    gemm_mma<true, true><<<dim3(HID / BN, BSZ / BM), 256, GEMM_SMEM>>>(
        (const __nv_bfloat16*)xh, (const __nv_bfloat16*)xl,
        (const __nv_bfloat16*)w1h, (const __nv_bfloat16*)w1l, b1,
        (__nv_bfloat16*)h1h, (__nv_bfloat16*)h1l, nullptr, BSZ, HID, IN_DIM);
    // GEMM2: h2 = relu(h1@w2+b2)  [4096,1024] K=2048
    gemm_mma<true, true><<<dim3(H2 / BN, BSZ / BM), 256, GEMM_SMEM>>>(
        (const __nv_bfloat16*)h1h, (const __nv_bfloat16*)h1l,
        (const __nv_bfloat16*)w2h, (const __nv_bfloat16*)w2l, b2,
        (__nv_bfloat16*)h2h, (__nv_bfloat16*)h2l, nullptr, BSZ, H2, HID);
    // GEMM3: logits = h2@Wpack+bpack  [4096,1280] K=1024
    gemm_mma<false, false><<<dim3(NHC / BN, BSZ / BM), 256, GEMM_SMEM>>>(
        (const __nv_bfloat16*)h2h, (const __nv_bfloat16*)h2l,
        (const __nv_bfloat16*)wph, (const __nv_bfloat16*)wpl, (const float*)bp,
        nullptr, nullptr, (float*)lg, BSZ, NHC, H2);

    softmax_scatter<<<BSZ, 256>>>((const float*)lg, out);
}

// round 4
// speedup vs baseline: 2.4505x; 1.0545x over previous
#include <cuda_runtime.h>
#include <cuda_bf16.h>
#include <cstdint>

// ---------------------------------------------------------------------------
// Actor_22625887715353 — round 4: mma.sync bf16x3, CTA tile 128x256x32,
// 8 warps (2M x 4N, warp tile 64x64), 3-stage cp.async pipeline (144 KB).
//   h1 = relu(x@w1+b1); h2 = relu(h1@w2+b2); logits = h2@Wpack+bpack;
//   per-head softmax + interleaved scatter.
// Each GEMM: D = Ah*Bh + Ah*Bl + Al*Bh (bf16 frags, fp32 accum).
// ---------------------------------------------------------------------------

constexpr int BSZ = 4096, IN_DIM = 2048, HID = 2048, H2 = 1024, NHC = 1280;

// ---- device scratch (no cudaMalloc allowed) ----
__device__ __nv_bfloat16 g_xh[BSZ * IN_DIM], g_xl[BSZ * IN_DIM];
__device__ __nv_bfloat16 g_w1h[HID * IN_DIM], g_w1l[HID * IN_DIM];   // [N=2048,K=2048]
__device__ __nv_bfloat16 g_w2h[H2 * HID],   g_w2l[H2 * HID];         // [N=1024,K=2048]
__device__ __nv_bfloat16 g_wph[NHC * H2],   g_wpl[NHC * H2];         // [N=1280,K=1024]
__device__ __nv_bfloat16 g_h1h[BSZ * HID],  g_h1l[BSZ * HID];
__device__ __nv_bfloat16 g_h2h[BSZ * H2],   g_h2l[BSZ * H2];
__device__ float g_logits[BSZ * NHC];
__device__ float g_bpack[NHC];

// ===========================================================================
// Low-level helpers (family-agnostic sm_80+ ISA)
// ===========================================================================
__device__ __forceinline__ uint32_t cvta_s(const void* p) {
    uint32_t a;
    asm("{ .reg .u64 t; cvta.to.shared.u64 t, %1; cvt.u32.u64 %0, t; }" : "=r"(a) : "l"(p));
    return a;
}
#define CP16(d, s) asm volatile("cp.async.cg.shared.global [%0], [%1], 16;" :: "r"(d), "l"(s))
#define CP_COMMIT  asm volatile("cp.async.commit_group;")
#define CP_WAIT1   asm volatile("cp.async.wait_group 1;")
#define LDSM4(r0, r1, r2, r3, a) \
    asm volatile("ldmatrix.sync.aligned.m8n8.x4.shared.b16 {%0,%1,%2,%3}, [%4];" \
                 : "=r"(r0), "=r"(r1), "=r"(r2), "=r"(r3) : "r"(a))
#define MMA_BF16(d, a, b) \
    asm volatile("mma.sync.aligned.m16n8k16.row.col.f32.bf16.bf16.f32 " \
                 "{%0,%1,%2,%3},{%4,%5,%6,%7},{%8,%9},{%0,%1,%2,%3};" \
                 : "+f"((d)[0]), "+f"((d)[1]), "+f"((d)[2]), "+f"((d)[3]) \
                 : "r"((a)[0]), "r"((a)[1]), "r"((a)[2]), "r"((a)[3]), \
                   "r"((b)[0]), "r"((b)[1]))

// ===========================================================================
// GEMM: D[M,N] = A[M,K] @ B[N,K]^T (bf16x3) + bias, optional relu,
// output split bf16 hi/lo (SPLIT) or fp32 (!SPLIT).
// CTA 128x256, K-step 32, 256 thr (8 warps = 2M x 4N, warp tile 64x64),
// 3-stage cp.async pipeline.
// Smem tiles row-major [rows][32 bf16] = 64B/row; 16B chunk c of row r
// stored at chunk (c ^ ((r>>1)&3)) -> conflict-free ldmatrix + cp.async.
// ===========================================================================
constexpr int BM = 128, BN = 256, BK = 32, STAGES = 3;
constexpr int TBA = BM * 64;                 // 8 KB
constexpr int TBB = BN * 64;                 // 16 KB
constexpr int SM_AH = 0, SM_AL = TBA, SM_BH = 2 * TBA, SM_BL = 2 * TBA + TBB;
constexpr int STB = 2 * TBA + 2 * TBB;       // 48 KB per stage
constexpr int GEMM_SMEM = STAGES * STB;      // 144 KB

template <bool RELU, bool SPLIT>
__global__ __launch_bounds__(256, 1) void gemm_mma(
    const __nv_bfloat16* __restrict__ Ah, const __nv_bfloat16* __restrict__ Al,
    const __nv_bfloat16* __restrict__ Bh, const __nv_bfloat16* __restrict__ Bl,
    const float* __restrict__ bias,
    __nv_bfloat16* __restrict__ oh, __nv_bfloat16* __restrict__ ol,
    float* __restrict__ of, int M, int N, int K)
{
    extern __shared__ char smem[];
    const uint32_t sb = cvta_s(smem);
    const int tid = threadIdx.x, lane = tid & 31, warp = tid >> 5;
    const int bm = blockIdx.y * BM, bn = blockIdx.x * BN;
    const int m0w = (warp >> 2) * 64, n0w = (warp & 3) * 64;

    // ---- cp.async mapping: thread t -> chunk (t&3) of rows (t>>2)+64h
    const int lr = tid >> 2, lc = tid & 3;

    auto load_stage = [&](int s, int kc) {
        const uint32_t stb = sb + s * STB;
        const int kg = kc * BK + lc * 8;
        const __nv_bfloat16* ga[2] = {Ah, Al};
        const __nv_bfloat16* gb[2] = {Bh, Bl};
#pragma unroll
        for (int t = 0; t < 2; t++)
#pragma unroll
            for (int h = 0; h < 2; h++) {
                const int r = lr + h * 64;
                const uint32_t d = stb + (t ? SM_AL : SM_AH) + r * 64 +
                                   ((lc ^ ((r >> 1) & 3)) << 4);
                CP16(d, ga[t] + (size_t)(bm + r) * K + kg);
            }
#pragma unroll
        for (int t = 0; t < 2; t++)
#pragma unroll
            for (int h = 0; h < 4; h++) {
                const int r = lr + h * 64;
                const uint32_t d = stb + (t ? SM_BL : SM_BH) + r * 64 +
                                   ((lc ^ ((r >> 1) & 3)) << 4);
                CP16(d, gb[t] + (size_t)(bn + r) * K + kg);
            }
    };

    float acc[4][8][4];
#pragma unroll
    for (int a = 0; a < 4; a++)
#pragma unroll
        for (int b = 0; b < 8; b++)
#pragma unroll
            for (int c = 0; c < 4; c++) acc[a][b][c] = 0.f;

    const int NS = K / BK;
    load_stage(0, 0); CP_COMMIT;
    load_stage(1, 1); CP_COMMIT;

    // ldmatrix lane geometry (validated in round 3)
    const int rA = lane & 15;                         // row within 16-row mfrag
    const int hA = lane >> 4;                         // k half
    const int rB = (lane & 7) + ((lane >> 4) << 3);   // row within 16-row nfrag pair
    const int hB = (lane >> 3) & 1;                   // k half

    int s_cur = 0, s_load = 2;
    for (int i = 0; i < NS; i++) {
        CP_WAIT1;
        __syncthreads();                 // stage i ready; slot s_load free (read in i-1)
        if (i + 2 < NS) load_stage(s_load, i + 2);
        CP_COMMIT;
        if (++s_load == STAGES) s_load = 0;

        const uint32_t stb = sb + s_cur * STB;
        if (++s_cur == STAGES) s_cur = 0;
#pragma unroll
        for (int ks = 0; ks < 2; ks++) {
            uint32_t ahf[4][4], alf[4][4], bhf[8][2], blf[8][2];
            // phase 1: A-hi + B-hi/lo fragments
#pragma unroll
            for (int mf = 0; mf < 4; mf++) {
                const int r = m0w + mf * 16 + rA;
                const uint32_t off = r * 64 + (((ks * 2 + hA) ^ ((r >> 1) & 3)) << 4);
                LDSM4(ahf[mf][0], ahf[mf][1], ahf[mf][2], ahf[mf][3], stb + SM_AH + off);
            }
#pragma unroll
            for (int p = 0; p < 4; p++) {
                const int r = n0w + p * 16 + rB;
                const uint32_t off = r * 64 + (((ks * 2 + hB) ^ ((r >> 1) & 3)) << 4);
                uint32_t q0, q1, q2, q3;
                LDSM4(q0, q1, q2, q3, stb + SM_BH + off);
                bhf[2 * p][0] = q0; bhf[2 * p][1] = q1;
                bhf[2 * p + 1][0] = q2; bhf[2 * p + 1][1] = q3;
                LDSM4(q0, q1, q2, q3, stb + SM_BL + off);
                blf[2 * p][0] = q0; blf[2 * p][1] = q1;
                blf[2 * p + 1][0] = q2; blf[2 * p + 1][1] = q3;
            }
#pragma unroll
            for (int mf = 0; mf < 4; mf++)
#pragma unroll
                for (int nf = 0; nf < 8; nf++) MMA_BF16(acc[mf][nf], ahf[mf], bhf[nf]);
#pragma unroll
            for (int mf = 0; mf < 4; mf++)
#pragma unroll
                for (int nf = 0; nf < 8; nf++) MMA_BF16(acc[mf][nf], ahf[mf], blf[nf]);
            // phase 2: A-lo fragments (blf now dead -> lower live pressure)
#pragma unroll
            for (int mf = 0; mf < 4; mf++) {
                const int r = m0w + mf * 16 + rA;
                const uint32_t off = r * 64 + (((ks * 2 + hA) ^ ((r >> 1) & 3)) << 4);
                LDSM4(alf[mf][0], alf[mf][1], alf[mf][2], alf[mf][3], stb + SM_AL + off);
            }
#pragma unroll
            for (int mf = 0; mf < 4; mf++)
#pragma unroll
                for (int nf = 0; nf < 8; nf++) MMA_BF16(acc[mf][nf], alf[mf], bhf[nf]);
        }
    }

    // ---- epilogue: bias (+relu), split bf16 hi/lo or fp32 ----
#pragma unroll
    for (int mf = 0; mf < 4; mf++)
#pragma unroll
        for (int nf = 0; nf < 8; nf++) {
            const int col = bn + n0w + nf * 8 + (lane & 3) * 2;
            const float bx = __ldg(bias + col), by = __ldg(bias + col + 1);
#pragma unroll
            for (int h = 0; h < 2; h++) {
                const int row = bm + m0w + mf * 16 + (lane >> 2) + h * 8;
                float v0 = acc[mf][nf][2 * h]     + bx;
                float v1 = acc[mf][nf][2 * h + 1] + by;
                if (RELU) { v0 = fmaxf(v0, 0.f); v1 = fmaxf(v1, 0.f); }
                if (SPLIT) {
                    __nv_bfloat162 ph, pl;
                    ph.x = __float2bfloat16(v0); ph.y = __float2bfloat16(v1);
                    pl.x = __float2bfloat16(v0 - __bfloat162float(ph.x));
                    pl.y = __float2bfloat16(v1 - __bfloat162float(ph.y));
                    *(__nv_bfloat162*)(oh + (size_t)row * N + col) = ph;
                    *(__nv_bfloat162*)(ol + (size_t)row * N + col) = pl;
                } else {
                    *(float2*)(of + (size_t)row * N + col) = make_float2(v0, v1);
                }
            }
        }
}

// ===========================================================================
// Conversion kernels
// ===========================================================================
__global__ void split_fp32(const float* __restrict__ in, __nv_bfloat16* __restrict__ oh,
                           __nv_bfloat16* __restrict__ ol, int n)
{
    int i = (blockIdx.x * blockDim.x + threadIdx.x) * 4;
    if (i >= n) return;
    float4 v = *(const float4*)(in + i);
    float vv[4] = {v.x, v.y, v.z, v.w};
    __nv_bfloat16 h[4], l[4];
#pragma unroll
    for (int j = 0; j < 4; j++) {
        h[j] = __float2bfloat16(vv[j]);
        l[j] = __float2bfloat16(vv[j] - __bfloat162float(h[j]));
    }
    __nv_bfloat162 h01, h23, l01, l23;
    h01.x = h[0]; h01.y = h[1]; h23.x = h[2]; h23.y = h[3];
    l01.x = l[0]; l01.y = l[1]; l23.x = l[2]; l23.y = l[3];
    *(__nv_bfloat162*)(oh + i)     = h01;
    *(__nv_bfloat162*)(oh + i + 2) = h23;
    *(__nv_bfloat162*)(ol + i)     = l01;
    *(__nv_bfloat162*)(ol + i + 2) = l23;
}

// in: [R, C] fp32 -> out: [C, R] bf16 hi/lo  (weights -> [N rows, K cols])
__global__ void transpose_split(const float* __restrict__ in, __nv_bfloat16* __restrict__ oh,
                                __nv_bfloat16* __restrict__ ol, int R, int C)
{
    __shared__ float t[32][33];
    const int c0 = blockIdx.x * 32, r0 = blockIdx.y * 32;
    const int tx = threadIdx.x, ty = threadIdx.y;
#pragma unroll
    for (int k = 0; k < 4; k++)
        t[ty + 8 * k][tx] = in[(size_t)(r0 + ty + 8 * k) * C + c0 + tx];
    __syncthreads();
#pragma unroll
    for (int k = 0; k < 4; k++) {
        float v = t[tx][ty + 8 * k];
        __nv_bfloat16 h = __float2bfloat16(v);
        size_t o = (size_t)(c0 + ty + 8 * k) * R + r0 + tx;
        oh[o] = h;
        ol[o] = __float2bfloat16(v - __bfloat162float(h));
    }
}

// Pack head weights into [NHC=1280 rows (N), H2=1024 cols (K)] bf16 hi/lo + bias.
__global__ void pack_heads_t(const float* __restrict__ wr, const float* __restrict__ br,
                             const float* __restrict__ wl, const float* __restrict__ bl)
{
    int idx = blockIdx.x * blockDim.x + threadIdx.x;
    if (idx < NHC * H2) {
        int c = idx / H2, h = idx % H2;
        float v;
        if (c < 1024) { int k = c >> 5, r = c & 31; v = wr[((size_t)k * H2 + h) * 32 + r]; }
        else { int cc = c - 1024; int k = cc >> 3, l = cc & 7; v = wl[((size_t)k * H2 + h) * 8 + l]; }
        __nv_bfloat16 hi = __float2bfloat16(v);
        g_wph[idx] = hi;
        g_wpl[idx] = __float2bfloat16(v - __bfloat162float(hi));
    }
    if (idx < NHC) g_bpack[idx] = (idx < 1024) ? br[idx] : bl[idx - 1024];
}

// ===========================================================================
// Softmax per head + interleaved scatter
// ===========================================================================
__global__ __launch_bounds__(256) void softmax_scatter(
    const float* __restrict__ logits, float* __restrict__ out)
{
    const int b = blockIdx.x, tid = threadIdx.x;
    const float* row = logits + (size_t)b * NHC;
    float* orow = out + (size_t)b * NHC;
    const int lane = tid & 31, warp = tid >> 5;
#pragma unroll
    for (int it = 0; it < 4; it++) {
        int k = warp + it * 8;
        float v = row[k * 32 + lane];
        float m = v;
#pragma unroll
        for (int o = 16; o; o >>= 1) m = fmaxf(m, __shfl_xor_sync(0xffffffffu, m, o));
        float e = __expf(v - m);
        float s = e;
#pragma unroll
        for (int o = 16; o; o >>= 1) s += __shfl_xor_sync(0xffffffffu, s, o);
        orow[(k >> 1) * 80 + (k & 1) * 32 + lane] = e / s;
    }
    {
        int g = tid >> 3, l8 = tid & 7;
        float v = row[1024 + g * 8 + l8];
        float m = v;
#pragma unroll
        for (int o = 4; o; o >>= 1) m = fmaxf(m, __shfl_xor_sync(0xffffffffu, m, o));
        float e = __expf(v - m);
        float s = e;
#pragma unroll
        for (int o = 4; o; o >>= 1) s += __shfl_xor_sync(0xffffffffu, s, o);
        orow[(g >> 1) * 80 + 64 + (g & 1) * 8 + l8] = e / s;
    }
}

// ===========================================================================
// Host side
// ===========================================================================
extern "C" void kernel_launch(void* const* d_in, const int* in_sizes, int n_in,
                              void* d_out, int out_size)
{
    const float* x  = (const float*)d_in[0];
    const float* w1 = (const float*)d_in[1];
    const float* b1 = (const float*)d_in[2];
    const float* w2 = (const float*)d_in[3];
    const float* b2 = (const float*)d_in[4];
    const float* wr = (const float*)d_in[5];
    const float* br = (const float*)d_in[6];
    const float* wl = (const float*)d_in[7];
    const float* bl = (const float*)d_in[8];
    float* out = (float*)d_out;

    void *xh, *xl, *w1h, *w1l, *w2h, *w2l, *wph, *wpl, *h1h, *h1l, *h2h, *h2l, *lg, *bp;
    cudaGetSymbolAddress(&xh, g_xh);   cudaGetSymbolAddress(&xl, g_xl);
    cudaGetSymbolAddress(&w1h, g_w1h); cudaGetSymbolAddress(&w1l, g_w1l);
    cudaGetSymbolAddress(&w2h, g_w2h); cudaGetSymbolAddress(&w2l, g_w2l);
    cudaGetSymbolAddress(&wph, g_wph); cudaGetSymbolAddress(&wpl, g_wpl);
    cudaGetSymbolAddress(&h1h, g_h1h); cudaGetSymbolAddress(&h1l, g_h1l);
    cudaGetSymbolAddress(&h2h, g_h2h); cudaGetSymbolAddress(&h2l, g_h2l);
    cudaGetSymbolAddress(&lg, g_logits); cudaGetSymbolAddress(&bp, g_bpack);

    cudaFuncSetAttribute(gemm_mma<true, true>,
                         cudaFuncAttributeMaxDynamicSharedMemorySize, GEMM_SMEM);
    cudaFuncSetAttribute(gemm_mma<false, false>,
                         cudaFuncAttributeMaxDynamicSharedMemorySize, GEMM_SMEM);

    // conversions (ordered so the ncu-profiled launch slot lands on GEMM1)
    split_fp32<<<(BSZ * IN_DIM / 4 + 255) / 256, 256>>>(
        x, (__nv_bfloat16*)xh, (__nv_bfloat16*)xl, BSZ * IN_DIM);
    transpose_split<<<dim3(HID / 32, IN_DIM / 32), dim3(32, 8)>>>(
        w1, (__nv_bfloat16*)w1h, (__nv_bfloat16*)w1l, IN_DIM, HID);
    transpose_split<<<dim3(H2 / 32, HID / 32), dim3(32, 8)>>>(
        w2, (__nv_bfloat16*)w2h, (__nv_bfloat16*)w2l, HID, H2);

    // GEMM1: h1 = relu(x@w1+b1)   [4096,2048] K=2048
    gemm_mma<true, true><<<dim3(HID / BN, BSZ / BM), 256, GEMM_SMEM>>>(
        (const __nv_bfloat16*)xh, (const __nv_bfloat16*)xl,
        (const __nv_bfloat16*)w1h, (const __nv_bfloat16*)w1l, b1,
        (__nv_bfloat16*)h1h, (__nv_bfloat16*)h1l, nullptr, BSZ, HID, IN_DIM);

    pack_heads_t<<<(NHC * H2 + 255) / 256, 256>>>(wr, br, wl, bl);

    // GEMM2: h2 = relu(h1@w2+b2)  [4096,1024] K=2048
    gemm_mma<true, true><<<dim3(H2 / BN, BSZ / BM), 256, GEMM_SMEM>>>(
        (const __nv_bfloat16*)h1h, (const __nv_bfloat16*)h1l,
        (const __nv_bfloat16*)w2h, (const __nv_bfloat16*)w2l, b2,
        (__nv_bfloat16*)h2h, (__nv_bfloat16*)h2l, nullptr, BSZ, H2, HID);
    // GEMM3: logits = h2@Wpack+bpack  [4096,1280] K=1024  (NHC/BN = 5)
    gemm_mma<false, false><<<dim3(NHC / BN, BSZ / BM), 256, GEMM_SMEM>>>(
        (const __nv_bfloat16*)h2h, (const __nv_bfloat16*)h2l,
        (const __nv_bfloat16*)wph, (const __nv_bfloat16*)wpl, (const float*)bp,
        nullptr, nullptr, (float*)lg, BSZ, NHC, H2);

    softmax_scatter<<<BSZ, 256>>>((const float*)lg, out);
}

// round 5
// speedup vs baseline: 3.2189x; 1.3136x over previous
#include <cuda_runtime.h>
#include <cuda_fp16.h>
#include <cstdint>

// ---------------------------------------------------------------------------
// Actor_22625887715353 — round 5: fp16 two-term split-precision mma.sync.
//   D = Ah*Bh + (Ah*2^-12)*((B-Bh)*2^12) = Ah*B  (weights exact, activations
//   fp16-rounded; dropped term Al*B ~ 2^-12 rel). fp32 accumulate.
// CTA 128x256x32, 8 warps (2Mx4N, warp tile 64x64), 4-stage cp.async (160KB).
//   h1 = relu(x@w1+b1); h2 = relu(h1@w2+b2); logits = h2@Wpack+bpack;
//   per-head softmax + interleaved scatter.
// ---------------------------------------------------------------------------

constexpr int BSZ = 4096, IN_DIM = 2048, HID = 2048, H2 = 1024, NHC = 1280;

// ---- device scratch (no cudaMalloc allowed) ----
__device__ __half g_xh[BSZ * IN_DIM];
__device__ __half g_w1h[HID * IN_DIM], g_w1ls[HID * IN_DIM];   // [N=2048,K=2048]
__device__ __half g_w2h[H2 * HID],    g_w2ls[H2 * HID];        // [N=1024,K=2048]
__device__ __half g_wph[NHC * H2],    g_wpls[NHC * H2];        // [N=1280,K=1024]
__device__ __half g_h1h[BSZ * HID];
__device__ __half g_h2h[BSZ * H2];
__device__ float g_logits[BSZ * NHC];
__device__ float g_bpack[NHC];

// ===========================================================================
// Low-level helpers (family-agnostic sm_80+ ISA)
// ===========================================================================
__device__ __forceinline__ uint32_t cvta_s(const void* p) {
    uint32_t a;
    asm("{ .reg .u64 t; cvta.to.shared.u64 t, %1; cvt.u32.u64 %0, t; }" : "=r"(a) : "l"(p));
    return a;
}
#define CP16(d, s) asm volatile("cp.async.cg.shared.global [%0], [%1], 16;" :: "r"(d), "l"(s))
#define CP_COMMIT  asm volatile("cp.async.commit_group;")
#define CP_WAIT2   asm volatile("cp.async.wait_group 2;")
#define LDSM4(r0, r1, r2, r3, a) \
    asm volatile("ldmatrix.sync.aligned.m8n8.x4.shared.b16 {%0,%1,%2,%3}, [%4];" \
                 : "=r"(r0), "=r"(r1), "=r"(r2), "=r"(r3) : "r"(a))
#define MMA_F16(d, a, b) \
    asm volatile("mma.sync.aligned.m16n8k16.row.col.f32.f16.f16.f32 " \
                 "{%0,%1,%2,%3},{%4,%5,%6,%7},{%8,%9},{%0,%1,%2,%3};" \
                 : "+f"((d)[0]), "+f"((d)[1]), "+f"((d)[2]), "+f"((d)[3]) \
                 : "r"((a)[0]), "r"((a)[1]), "r"((a)[2]), "r"((a)[3]), \
                   "r"((b)[0]), "r"((b)[1]))
__device__ __forceinline__ uint32_t mulh2(uint32_t a, uint32_t b) {
    uint32_t r; asm("mul.rn.f16x2 %0, %1, %2;" : "=r"(r) : "r"(a), "r"(b)); return r;
}
constexpr uint32_t H2_2PM12 = 0x0C000C00u;   // half2(2^-12, 2^-12)

// ===========================================================================
// GEMM: D[M,N] = A[M,K] @ B[N,K]^T + bias; A fp16, B = (Bh, Bls=(B-Bh)*2^12).
// Output fp16 (SPLIT) or fp32 (!SPLIT). Optional relu.
// CTA 128x256, K-step 32, 256 thr (8 warps = 2M x 4N, warp tile 64x64),
// 4-stage cp.async pipeline.
// Smem tiles row-major [rows][32 halves] = 64B/row; 16B chunk c of row r
// stored at chunk (c ^ ((r>>1)&3)) -> conflict-free ldmatrix + cp.async.
// ===========================================================================
constexpr int BM = 128, BN = 256, BK = 32, STAGES = 4;
constexpr int TBA = BM * 64;                   // 8 KB
constexpr int TBB = BN * 64;                   // 16 KB
constexpr int SM_AH = 0, SM_BH = TBA, SM_BLS = TBA + TBB;
constexpr int STB = TBA + 2 * TBB;             // 40 KB per stage
constexpr int GEMM_SMEM = STAGES * STB;        // 160 KB

template <bool RELU, bool SPLIT>
__global__ __launch_bounds__(256, 1) void gemm_mma(
    const __half* __restrict__ Ah,
    const __half* __restrict__ Bh, const __half* __restrict__ Bls,
    const float* __restrict__ bias,
    __half* __restrict__ oh, float* __restrict__ of, int M, int N, int K)
{
    extern __shared__ char smem[];
    const uint32_t sb = cvta_s(smem);
    const int tid = threadIdx.x, lane = tid & 31, warp = tid >> 5;
    const int bm = blockIdx.y * BM, bn = blockIdx.x * BN;
    const int m0w = (warp >> 2) * 64, n0w = (warp & 3) * 64;

    // cp.async mapping: thread t -> 16B chunk (t&3) of rows (t>>2)+64h
    const int lr = tid >> 2, lc = tid & 3;

    auto load_stage = [&](int s, int kc) {
        const uint32_t stb = sb + s * STB;
        const int kg = kc * BK + lc * 8;
#pragma unroll
        for (int h = 0; h < 2; h++) {
            const int r = lr + h * 64;
            const uint32_t d = stb + SM_AH + r * 64 + ((lc ^ ((r >> 1) & 3)) << 4);
            CP16(d, Ah + (size_t)(bm + r) * K + kg);
        }
#pragma unroll
        for (int h = 0; h < 4; h++) {
            const int r = lr + h * 64;
            const uint32_t sw = r * 64 + ((lc ^ ((r >> 1) & 3)) << 4);
            CP16(stb + SM_BH + sw,  Bh  + (size_t)(bn + r) * K + kg);
            CP16(stb + SM_BLS + sw, Bls + (size_t)(bn + r) * K + kg);
        }
    };

    float acc[4][8][4];
#pragma unroll
    for (int a = 0; a < 4; a++)
#pragma unroll
        for (int b = 0; b < 8; b++)
#pragma unroll
            for (int c = 0; c < 4; c++) acc[a][b][c] = 0.f;

    const int NS = K / BK;
    load_stage(0, 0); CP_COMMIT;
    load_stage(1, 1); CP_COMMIT;
    load_stage(2, 2); CP_COMMIT;

    // ldmatrix lane geometry (validated rounds 3-4)
    const int rA = lane & 15;                         // row within 16-row mfrag
    const int hA = lane >> 4;                         // k half
    const int rB = (lane & 7) + ((lane >> 4) << 3);   // row within 16-row nfrag pair
    const int hB = (lane >> 3) & 1;                   // k half

    int s_cur = 0, s_load = 3;
    for (int i = 0; i < NS; i++) {
        CP_WAIT2;                        // stage i complete ({i+1,i+2} may pend)
        __syncthreads();
        if (i + 3 < NS) load_stage(s_load, i + 3);
        CP_COMMIT;
        if (++s_load == STAGES) s_load = 0;

        const uint32_t stb = sb + s_cur * STB;
        if (++s_cur == STAGES) s_cur = 0;
#pragma unroll
        for (int ks = 0; ks < 2; ks++) {
            uint32_t ahf[4][4], bf[8][2];
#pragma unroll
            for (int mf = 0; mf < 4; mf++) {
                const int r = m0w + mf * 16 + rA;
                const uint32_t off = r * 64 + (((ks * 2 + hA) ^ ((r >> 1) & 3)) << 4);
                LDSM4(ahf[mf][0], ahf[mf][1], ahf[mf][2], ahf[mf][3], stb + SM_AH + off);
            }
#pragma unroll
            for (int p = 0; p < 4; p++) {
                const int r = n0w + p * 16 + rB;
                const uint32_t off = r * 64 + (((ks * 2 + hB) ^ ((r >> 1) & 3)) << 4);
                uint32_t q0, q1, q2, q3;
                LDSM4(q0, q1, q2, q3, stb + SM_BH + off);
                bf[2 * p][0] = q0; bf[2 * p][1] = q1;
                bf[2 * p + 1][0] = q2; bf[2 * p + 1][1] = q3;
            }
            // term 1: Ah * Bh
#pragma unroll
            for (int mf = 0; mf < 4; mf++)
#pragma unroll
                for (int nf = 0; nf < 8; nf++) MMA_F16(acc[mf][nf], ahf[mf], bf[nf]);
            // reload B-frags from Bls (overwrite), scale A-frags by 2^-12
#pragma unroll
            for (int p = 0; p < 4; p++) {
                const int r = n0w + p * 16 + rB;
                const uint32_t off = r * 64 + (((ks * 2 + hB) ^ ((r >> 1) & 3)) << 4);
                uint32_t q0, q1, q2, q3;
                LDSM4(q0, q1, q2, q3, stb + SM_BLS + off);
                bf[2 * p][0] = q0; bf[2 * p][1] = q1;
                bf[2 * p + 1][0] = q2; bf[2 * p + 1][1] = q3;
            }
#pragma unroll
            for (int mf = 0; mf < 4; mf++)
#pragma unroll
                for (int j = 0; j < 4; j++) ahf[mf][j] = mulh2(ahf[mf][j], H2_2PM12);
            // term 2: (Ah*2^-12) * (Bl*2^12) = Ah * Bl
#pragma unroll
            for (int mf = 0; mf < 4; mf++)
#pragma unroll
                for (int nf = 0; nf < 8; nf++) MMA_F16(acc[mf][nf], ahf[mf], bf[nf]);
        }
    }

    // ---- epilogue: bias (+relu), fp16 or fp32 stores ----
#pragma unroll
    for (int mf = 0; mf < 4; mf++)
#pragma unroll
        for (int nf = 0; nf < 8; nf++) {
            const int col = bn + n0w + nf * 8 + (lane & 3) * 2;
            const float bx = __ldg(bias + col), by = __ldg(bias + col + 1);
#pragma unroll
            for (int h = 0; h < 2; h++) {
                const int row = bm + m0w + mf * 16 + (lane >> 2) + h * 8;
                float v0 = acc[mf][nf][2 * h]     + bx;
                float v1 = acc[mf][nf][2 * h + 1] + by;
                if (RELU) { v0 = fmaxf(v0, 0.f); v1 = fmaxf(v1, 0.f); }
                if (SPLIT) {
                    __half2 p;
                    p.x = __float2half_rn(v0); p.y = __float2half_rn(v1);
                    *(__half2*)(oh + (size_t)row * N + col) = p;
                } else {
                    *(float2*)(of + (size_t)row * N + col) = make_float2(v0, v1);
                }
            }
        }
}

// ===========================================================================
// Conversion kernels
// ===========================================================================
__global__ void cast_fp16(const float* __restrict__ in, __half* __restrict__ oh, int n)
{
    int i = (blockIdx.x * blockDim.x + threadIdx.x) * 4;
    if (i >= n) return;
    float4 v = *(const float4*)(in + i);
    __half2 a, b;
    a.x = __float2half_rn(v.x); a.y = __float2half_rn(v.y);
    b.x = __float2half_rn(v.z); b.y = __float2half_rn(v.w);
    *(__half2*)(oh + i) = a;
    *(__half2*)(oh + i + 2) = b;
}

// in: [R, C] fp32 -> out: [C, R] fp16 hi + scaled-lo  (weights -> [N rows, K cols])
__global__ void transpose_split(const float* __restrict__ in, __half* __restrict__ oh,
                                __half* __restrict__ ols, int R, int C)
{
    __shared__ float t[32][33];
    const int c0 = blockIdx.x * 32, r0 = blockIdx.y * 32;
    const int tx = threadIdx.x, ty = threadIdx.y;
#pragma unroll
    for (int k = 0; k < 4; k++)
        t[ty + 8 * k][tx] = in[(size_t)(r0 + ty + 8 * k) * C + c0 + tx];
    __syncthreads();
#pragma unroll
    for (int k = 0; k < 4; k++) {
        float v = t[tx][ty + 8 * k];
        __half h = __float2half_rn(v);
        size_t o = (size_t)(c0 + ty + 8 * k) * R + r0 + tx;
        oh[o]  = h;
        ols[o] = __float2half_rn((v - __half2float(h)) * 4096.0f);
    }
}

// Pack head weights into [NHC=1280 rows (N), H2=1024 cols (K)] hi + scaled-lo + bias.
__global__ void pack_heads_t(const float* __restrict__ wr, const float* __restrict__ br,
                             const float* __restrict__ wl, const float* __restrict__ bl)
{
    int idx = blockIdx.x * blockDim.x + threadIdx.x;
    if (idx < NHC * H2) {
        int c = idx / H2, h = idx % H2;
        float v;
        if (c < 1024) { int k = c >> 5, r = c & 31; v = wr[((size_t)k * H2 + h) * 32 + r]; }
        else { int cc = c - 1024; int k = cc >> 3, l = cc & 7; v = wl[((size_t)k * H2 + h) * 8 + l]; }
        __half hi = __float2half_rn(v);
        g_wph[idx]  = hi;
        g_wpls[idx] = __float2half_rn((v - __half2float(hi)) * 4096.0f);
    }
    if (idx < NHC) g_bpack[idx] = (idx < 1024) ? br[idx] : bl[idx - 1024];
}

// ===========================================================================
// Softmax per head + interleaved scatter
// ===========================================================================
__global__ __launch_bounds__(256) void softmax_scatter(
    const float* __restrict__ logits, float* __restrict__ out)
{
    const int b = blockIdx.x, tid = threadIdx.x;
    const float* row = logits + (size_t)b * NHC;
    float* orow = out + (size_t)b * NHC;
    const int lane = tid & 31, warp = tid >> 5;
#pragma unroll
    for (int it = 0; it < 4; it++) {
        int k = warp + it * 8;
        float v = row[k * 32 + lane];
        float m = v;
#pragma unroll
        for (int o = 16; o; o >>= 1) m = fmaxf(m, __shfl_xor_sync(0xffffffffu, m, o));
        float e = __expf(v - m);
        float s = e;
#pragma unroll
        for (int o = 16; o; o >>= 1) s += __shfl_xor_sync(0xffffffffu, s, o);
        orow[(k >> 1) * 80 + (k & 1) * 32 + lane] = e / s;
    }
    {
        int g = tid >> 3, l8 = tid & 7;
        float v = row[1024 + g * 8 + l8];
        float m = v;
#pragma unroll
        for (int o = 4; o; o >>= 1) m = fmaxf(m, __shfl_xor_sync(0xffffffffu, m, o));
        float e = __expf(v - m);
        float s = e;
#pragma unroll
        for (int o = 4; o; o >>= 1) s += __shfl_xor_sync(0xffffffffu, s, o);
        orow[(g >> 1) * 80 + 64 + (g & 1) * 8 + l8] = e / s;
    }
}

// ===========================================================================
// Host side
// ===========================================================================
extern "C" void kernel_launch(void* const* d_in, const int* in_sizes, int n_in,
                              void* d_out, int out_size)
{
    const float* x  = (const float*)d_in[0];
    const float* w1 = (const float*)d_in[1];
    const float* b1 = (const float*)d_in[2];
    const float* w2 = (const float*)d_in[3];
    const float* b2 = (const float*)d_in[4];
    const float* wr = (const float*)d_in[5];
    const float* br = (const float*)d_in[6];
    const float* wl = (const float*)d_in[7];
    const float* bl = (const float*)d_in[8];
    float* out = (float*)d_out;

    void *xh, *w1h, *w1ls, *w2h, *w2ls, *wph, *wpls, *h1h, *h2h, *lg, *bp;
    cudaGetSymbolAddress(&xh, g_xh);
    cudaGetSymbolAddress(&w1h, g_w1h); cudaGetSymbolAddress(&w1ls, g_w1ls);
    cudaGetSymbolAddress(&w2h, g_w2h); cudaGetSymbolAddress(&w2ls, g_w2ls);
    cudaGetSymbolAddress(&wph, g_wph); cudaGetSymbolAddress(&wpls, g_wpls);
    cudaGetSymbolAddress(&h1h, g_h1h); cudaGetSymbolAddress(&h2h, g_h2h);
    cudaGetSymbolAddress(&lg, g_logits); cudaGetSymbolAddress(&bp, g_bpack);

    cudaFuncSetAttribute(gemm_mma<true, true>,
                         cudaFuncAttributeMaxDynamicSharedMemorySize, GEMM_SMEM);
    cudaFuncSetAttribute(gemm_mma<false, false>,
                         cudaFuncAttributeMaxDynamicSharedMemorySize, GEMM_SMEM);

    // conversions (ordered so the ncu-profiled launch slot lands on GEMM1)
    cast_fp16<<<(BSZ * IN_DIM / 4 + 255) / 256, 256>>>(x, (__half*)xh, BSZ * IN_DIM);
    transpose_split<<<dim3(HID / 32, IN_DIM / 32), dim3(32, 8)>>>(
        w1, (__half*)w1h, (__half*)w1ls, IN_DIM, HID);
    transpose_split<<<dim3(H2 / 32, HID / 32), dim3(32, 8)>>>(
        w2, (__half*)w2h, (__half*)w2ls, HID, H2);

    // GEMM1: h1 = relu(x@w1+b1)   [4096,2048] K=2048
    gemm_mma<true, true><<<dim3(HID / BN, BSZ / BM), 256, GEMM_SMEM>>>(
        (const __half*)xh, (const __half*)w1h, (const __half*)w1ls, b1,
        (__half*)h1h, nullptr, BSZ, HID, IN_DIM);

    pack_heads_t<<<(NHC * H2 + 255) / 256, 256>>>(wr, br, wl, bl);

    // GEMM2: h2 = relu(h1@w2+b2)  [4096,1024] K=2048
    gemm_mma<true, true><<<dim3(H2 / BN, BSZ / BM), 256, GEMM_SMEM>>>(
        (const __half*)h1h, (const __half*)w2h, (const __half*)w2ls, b2,
        (__half*)h2h, nullptr, BSZ, H2, HID);
    // GEMM3: logits = h2@Wpack+bpack  [4096,1280] K=1024
    gemm_mma<false, false><<<dim3(NHC / BN, BSZ / BM), 256, GEMM_SMEM>>>(
        (const __half*)h2h, (const __half*)wph, (const __half*)wpls, (const float*)bp,
        nullptr, (float*)lg, BSZ, NHC, H2);

    softmax_scatter<<<BSZ, 256>>>((const float*)lg, out);
}

// round 6
// speedup vs baseline: 5.4348x; 1.6884x over previous
#include <cuda_runtime.h>
#include <cuda_fp16.h>
#include <cstdint>

// ---------------------------------------------------------------------------
// Actor_22625887715353 — round 6: plain fp16 mma.sync GEMMs (fp32 accum).
//   Measured round-5 error budget: A-side fp16 rounding alone -> 3.3e-5.
//   Dropping the B correction term adds a comparable independent error;
//   predicted ~1e-4 vs 1e-3 budget. MMA count halves.
// CTA 128x256, K-step 64 (2 x 32 subtiles), 8 warps (2Mx4N, 64x64 warp tile),
// 3-stage cp.async pipeline (144 KB smem).
//   h1 = relu(x@w1+b1); h2 = relu(h1@w2+b2); logits = h2@Wpack+bpack;
//   per-head softmax + interleaved scatter.
// ---------------------------------------------------------------------------

constexpr int BSZ = 4096, IN_DIM = 2048, HID = 2048, H2 = 1024, NHC = 1280;

// ---- device scratch (no cudaMalloc allowed) ----
__device__ __half g_xh[BSZ * IN_DIM];
__device__ __half g_w1h[HID * IN_DIM];     // [N=2048, K=2048]
__device__ __half g_w2h[H2 * HID];         // [N=1024, K=2048]
__device__ __half g_wph[NHC * H2];         // [N=1280, K=1024]
__device__ __half g_h1h[BSZ * HID];
__device__ __half g_h2h[BSZ * H2];
__device__ float g_logits[BSZ * NHC];
__device__ float g_bpack[NHC];

// ===========================================================================
// Low-level helpers (family-agnostic sm_80+ ISA)
// ===========================================================================
__device__ __forceinline__ uint32_t cvta_s(const void* p) {
    uint32_t a;
    asm("{ .reg .u64 t; cvta.to.shared.u64 t, %1; cvt.u32.u64 %0, t; }" : "=r"(a) : "l"(p));
    return a;
}
#define CP16(d, s) asm volatile("cp.async.cg.shared.global [%0], [%1], 16;" :: "r"(d), "l"(s))
#define CP_COMMIT  asm volatile("cp.async.commit_group;")
#define CP_WAIT1   asm volatile("cp.async.wait_group 1;")
#define LDSM4(r0, r1, r2, r3, a) \
    asm volatile("ldmatrix.sync.aligned.m8n8.x4.shared.b16 {%0,%1,%2,%3}, [%4];" \
                 : "=r"(r0), "=r"(r1), "=r"(r2), "=r"(r3) : "r"(a))
#define MMA_F16(d, a, b) \
    asm volatile("mma.sync.aligned.m16n8k16.row.col.f32.f16.f16.f32 " \
                 "{%0,%1,%2,%3},{%4,%5,%6,%7},{%8,%9},{%0,%1,%2,%3};" \
                 : "+f"((d)[0]), "+f"((d)[1]), "+f"((d)[2]), "+f"((d)[3]) \
                 : "r"((a)[0]), "r"((a)[1]), "r"((a)[2]), "r"((a)[3]), \
                   "r"((b)[0]), "r"((b)[1]))

// ===========================================================================
// GEMM: D[M,N] = A[M,K] @ B[N,K]^T + bias; A,B fp16, fp32 accumulate.
// Output fp16 (SPLIT) or fp32 (!SPLIT). Optional relu.
// CTA 128x256, K-step 64 as two 32-wide subtiles, 256 thr (8 warps = 2Mx4N,
// warp tile 64x64), 3-stage cp.async pipeline.
// Smem subtiles row-major [rows][32 halves] = 64B/row; 16B chunk c of row r
// stored at chunk (c ^ ((r>>1)&3)) -> conflict-free ldmatrix + cp.async.
// ===========================================================================
constexpr int BM = 128, BN = 256, BK = 64, STAGES = 3;
constexpr int TBA = BM * 64;                   // 8 KB  (one 32-wide A subtile)
constexpr int TBB = BN * 64;                   // 16 KB (one 32-wide B subtile)
constexpr int SM_A0 = 0, SM_A1 = TBA, SM_B0 = 2 * TBA, SM_B1 = 2 * TBA + TBB;
constexpr int STB = 2 * TBA + 2 * TBB;         // 48 KB per stage
constexpr int GEMM_SMEM = STAGES * STB;        // 144 KB

template <bool RELU, bool SPLIT>
__global__ __launch_bounds__(256, 1) void gemm_f16(
    const __half* __restrict__ Ah, const __half* __restrict__ Bh,
    const float* __restrict__ bias,
    __half* __restrict__ oh, float* __restrict__ of, int M, int N, int K)
{
    extern __shared__ char smem[];
    const uint32_t sb = cvta_s(smem);
    const int tid = threadIdx.x, lane = tid & 31, warp = tid >> 5;
    const int bm = blockIdx.y * BM, bn = blockIdx.x * BN;
    const int m0w = (warp >> 2) * 64, n0w = (warp & 3) * 64;

    // cp.async mapping: thread t -> 16B chunk (t&3) of rows (t>>2)+64h
    const int lr = tid >> 2, lc = tid & 3;

    auto load_stage = [&](int s, int kc) {    // kc counts 64-wide K chunks
        const uint32_t stb = sb + s * STB;
#pragma unroll
        for (int sub = 0; sub < 2; sub++) {
            const int kg = kc * BK + sub * 32 + lc * 8;
            const uint32_t sa = stb + (sub ? SM_A1 : SM_A0);
            const uint32_t sbb = stb + (sub ? SM_B1 : SM_B0);
#pragma unroll
            for (int h = 0; h < 2; h++) {
                const int r = lr + h * 64;
                CP16(sa + r * 64 + ((lc ^ ((r >> 1) & 3)) << 4),
                     Ah + (size_t)(bm + r) * K + kg);
            }
#pragma unroll
            for (int h = 0; h < 4; h++) {
                const int r = lr + h * 64;
                CP16(sbb + r * 64 + ((lc ^ ((r >> 1) & 3)) << 4),
                     Bh + (size_t)(bn + r) * K + kg);
            }
        }
    };

    float acc[4][8][4];
#pragma unroll
    for (int a = 0; a < 4; a++)
#pragma unroll
        for (int b = 0; b < 8; b++)
#pragma unroll
            for (int c = 0; c < 4; c++) acc[a][b][c] = 0.f;

    const int NS = K / BK;
    load_stage(0, 0); CP_COMMIT;
    load_stage(1, 1); CP_COMMIT;

    // ldmatrix lane geometry (validated rounds 3-5)
    const int rA = lane & 15;                         // row within 16-row mfrag
    const int hA = lane >> 4;                         // k half
    const int rB = (lane & 7) + ((lane >> 4) << 3);   // row within 16-row nfrag pair
    const int hB = (lane >> 3) & 1;                   // k half

    int s_cur = 0, s_load = 2;
    for (int i = 0; i < NS; i++) {
        CP_WAIT1;                         // stage i complete (i+1 may pend)
        __syncthreads();
        if (i + 2 < NS) load_stage(s_load, i + 2);   // slot read in iter i-1
        CP_COMMIT;
        if (++s_load == STAGES) s_load = 0;

        const uint32_t stb = sb + s_cur * STB;
        if (++s_cur == STAGES) s_cur = 0;
#pragma unroll
        for (int sub = 0; sub < 2; sub++) {
            const uint32_t sa = stb + (sub ? SM_A1 : SM_A0);
            const uint32_t sbb = stb + (sub ? SM_B1 : SM_B0);
#pragma unroll
            for (int ks = 0; ks < 2; ks++) {
                uint32_t ahf[4][4], bf[8][2];
#pragma unroll
                for (int mf = 0; mf < 4; mf++) {
                    const int r = m0w + mf * 16 + rA;
                    const uint32_t off = r * 64 + (((ks * 2 + hA) ^ ((r >> 1) & 3)) << 4);
                    LDSM4(ahf[mf][0], ahf[mf][1], ahf[mf][2], ahf[mf][3], sa + off);
                }
#pragma unroll
                for (int p = 0; p < 4; p++) {
                    const int r = n0w + p * 16 + rB;
                    const uint32_t off = r * 64 + (((ks * 2 + hB) ^ ((r >> 1) & 3)) << 4);
                    uint32_t q0, q1, q2, q3;
                    LDSM4(q0, q1, q2, q3, sbb + off);
                    bf[2 * p][0] = q0; bf[2 * p][1] = q1;
                    bf[2 * p + 1][0] = q2; bf[2 * p + 1][1] = q3;
                }
#pragma unroll
                for (int mf = 0; mf < 4; mf++)
#pragma unroll
                    for (int nf = 0; nf < 8; nf++) MMA_F16(acc[mf][nf], ahf[mf], bf[nf]);
            }
        }
    }

    // ---- epilogue: bias (+relu), fp16 or fp32 stores ----
#pragma unroll
    for (int mf = 0; mf < 4; mf++)
#pragma unroll
        for (int nf = 0; nf < 8; nf++) {
            const int col = bn + n0w + nf * 8 + (lane & 3) * 2;
            const float bx = __ldg(bias + col), by = __ldg(bias + col + 1);
#pragma unroll
            for (int h = 0; h < 2; h++) {
                const int row = bm + m0w + mf * 16 + (lane >> 2) + h * 8;
                float v0 = acc[mf][nf][2 * h]     + bx;
                float v1 = acc[mf][nf][2 * h + 1] + by;
                if (RELU) { v0 = fmaxf(v0, 0.f); v1 = fmaxf(v1, 0.f); }
                if (SPLIT) {
                    __half2 p;
                    p.x = __float2half_rn(v0); p.y = __float2half_rn(v1);
                    *(__half2*)(oh + (size_t)row * N + col) = p;
                } else {
                    *(float2*)(of + (size_t)row * N + col) = make_float2(v0, v1);
                }
            }
        }
}

// ===========================================================================
// Conversion kernels
// ===========================================================================
__global__ void cast_fp16(const float* __restrict__ in, __half* __restrict__ oh, int n)
{
    int i = (blockIdx.x * blockDim.x + threadIdx.x) * 4;
    if (i >= n) return;
    float4 v = *(const float4*)(in + i);
    __half2 a, b;
    a.x = __float2half_rn(v.x); a.y = __float2half_rn(v.y);
    b.x = __float2half_rn(v.z); b.y = __float2half_rn(v.w);
    *(__half2*)(oh + i) = a;
    *(__half2*)(oh + i + 2) = b;
}

// in: [R, C] fp32 -> out: [C, R] fp16  (weights -> [N rows, K cols])
__global__ void transpose_cast(const float* __restrict__ in, __half* __restrict__ oh,
                               int R, int C)
{
    __shared__ float t[32][33];
    const int c0 = blockIdx.x * 32, r0 = blockIdx.y * 32;
    const int tx = threadIdx.x, ty = threadIdx.y;
#pragma unroll
    for (int k = 0; k < 4; k++)
        t[ty + 8 * k][tx] = in[(size_t)(r0 + ty + 8 * k) * C + c0 + tx];
    __syncthreads();
#pragma unroll
    for (int k = 0; k < 4; k++)
        oh[(size_t)(c0 + ty + 8 * k) * R + r0 + tx] = __float2half_rn(t[tx][ty + 8 * k]);
}

// Pack head weights into [NHC=1280 rows (N), H2=1024 cols (K)] fp16 + bias.
__global__ void pack_heads_t(const float* __restrict__ wr, const float* __restrict__ br,
                             const float* __restrict__ wl, const float* __restrict__ bl)
{
    int idx = blockIdx.x * blockDim.x + threadIdx.x;
    if (idx < NHC * H2) {
        int c = idx / H2, h = idx % H2;
        float v;
        if (c < 1024) { int k = c >> 5, r = c & 31; v = wr[((size_t)k * H2 + h) * 32 + r]; }
        else { int cc = c - 1024; int k = cc >> 3, l = cc & 7; v = wl[((size_t)k * H2 + h) * 8 + l]; }
        g_wph[idx] = __float2half_rn(v);
    }
    if (idx < NHC) g_bpack[idx] = (idx < 1024) ? br[idx] : bl[idx - 1024];
}

// ===========================================================================
// Softmax per head + interleaved scatter
// ===========================================================================
__global__ __launch_bounds__(256) void softmax_scatter(
    const float* __restrict__ logits, float* __restrict__ out)
{
    const int b = blockIdx.x, tid = threadIdx.x;
    const float* row = logits + (size_t)b * NHC;
    float* orow = out + (size_t)b * NHC;
    const int lane = tid & 31, warp = tid >> 5;
#pragma unroll
    for (int it = 0; it < 4; it++) {
        int k = warp + it * 8;
        float v = row[k * 32 + lane];
        float m = v;
#pragma unroll
        for (int o = 16; o; o >>= 1) m = fmaxf(m, __shfl_xor_sync(0xffffffffu, m, o));
        float e = __expf(v - m);
        float s = e;
#pragma unroll
        for (int o = 16; o; o >>= 1) s += __shfl_xor_sync(0xffffffffu, s, o);
        orow[(k >> 1) * 80 + (k & 1) * 32 + lane] = e / s;
    }
    {
        int g = tid >> 3, l8 = tid & 7;
        float v = row[1024 + g * 8 + l8];
        float m = v;
#pragma unroll
        for (int o = 4; o; o >>= 1) m = fmaxf(m, __shfl_xor_sync(0xffffffffu, m, o));
        float e = __expf(v - m);
        float s = e;
#pragma unroll
        for (int o = 4; o; o >>= 1) s += __shfl_xor_sync(0xffffffffu, s, o);
        orow[(g >> 1) * 80 + 64 + (g & 1) * 8 + l8] = e / s;
    }
}

// ===========================================================================
// Host side
// ===========================================================================
extern "C" void kernel_launch(void* const* d_in, const int* in_sizes, int n_in,
                              void* d_out, int out_size)
{
    const float* x  = (const float*)d_in[0];
    const float* w1 = (const float*)d_in[1];
    const float* b1 = (const float*)d_in[2];
    const float* w2 = (const float*)d_in[3];
    const float* b2 = (const float*)d_in[4];
    const float* wr = (const float*)d_in[5];
    const float* br = (const float*)d_in[6];
    const float* wl = (const float*)d_in[7];
    const float* bl = (const float*)d_in[8];
    float* out = (float*)d_out;

    void *xh, *w1h, *w2h, *wph, *h1h, *h2h, *lg, *bp;
    cudaGetSymbolAddress(&xh, g_xh);
    cudaGetSymbolAddress(&w1h, g_w1h);
    cudaGetSymbolAddress(&w2h, g_w2h);
    cudaGetSymbolAddress(&wph, g_wph);
    cudaGetSymbolAddress(&h1h, g_h1h); cudaGetSymbolAddress(&h2h, g_h2h);
    cudaGetSymbolAddress(&lg, g_logits); cudaGetSymbolAddress(&bp, g_bpack);

    cudaFuncSetAttribute(gemm_f16<true, true>,
                         cudaFuncAttributeMaxDynamicSharedMemorySize, GEMM_SMEM);
    cudaFuncSetAttribute(gemm_f16<false, false>,
                         cudaFuncAttributeMaxDynamicSharedMemorySize, GEMM_SMEM);

    // conversions (ordered so the ncu-profiled launch slot lands on GEMM1)
    cast_fp16<<<(BSZ * IN_DIM / 4 + 255) / 256, 256>>>(x, (__half*)xh, BSZ * IN_DIM);
    transpose_cast<<<dim3(HID / 32, IN_DIM / 32), dim3(32, 8)>>>(w1, (__half*)w1h, IN_DIM, HID);
    transpose_cast<<<dim3(H2 / 32, HID / 32), dim3(32, 8)>>>(w2, (__half*)w2h, HID, H2);

    // GEMM1: h1 = relu(x@w1+b1)   [4096,2048] K=2048
    gemm_f16<true, true><<<dim3(HID / BN, BSZ / BM), 256, GEMM_SMEM>>>(
        (const __half*)xh, (const __half*)w1h, b1, (__half*)h1h, nullptr, BSZ, HID, IN_DIM);

    pack_heads_t<<<(NHC * H2 + 255) / 256, 256>>>(wr, br, wl, bl);

    // GEMM2: h2 = relu(h1@w2+b2)  [4096,1024] K=2048
    gemm_f16<true, true><<<dim3(H2 / BN, BSZ / BM), 256, GEMM_SMEM>>>(
        (const __half*)h1h, (const __half*)w2h, b2, (__half*)h2h, nullptr, BSZ, H2, HID);
    // GEMM3: logits = h2@Wpack+bpack  [4096,1280] K=1024
    gemm_f16<false, false><<<dim3(NHC / BN, BSZ / BM), 256, GEMM_SMEM>>>(
        (const __half*)h2h, (const __half*)wph, (const float*)bp,
        nullptr, (float*)lg, BSZ, NHC, H2);

    softmax_scatter<<<BSZ, 256>>>((const float*)lg, out);
}

// round 7
// speedup vs baseline: 6.0000x; 1.1040x over previous
#include <cuda_runtime.h>
#include <cuda_fp16.h>
#include <cstdint>

// ---------------------------------------------------------------------------
// Actor_22625887715353 — round 7: fp16 mma.sync, 2 CTAs/SM co-scheduling.
// CTA 128x128x64 (3-stage cp.async, 96 KB smem), __launch_bounds__(256,2)
// so two CTAs overlap each other's sync/dependency bubbles on one SM.
// 8 warps = 2M x 4N, warp tile 64x32.
//   h1 = relu(x@w1+b1); h2 = relu(h1@w2+b2); logits = h2@Wpack+bpack;
//   per-head softmax + interleaved scatter.
// ---------------------------------------------------------------------------

constexpr int BSZ = 4096, IN_DIM = 2048, HID = 2048, H2 = 1024, NHC = 1280;

// ---- device scratch (no cudaMalloc allowed) ----
__device__ __half g_xh[BSZ * IN_DIM];
__device__ __half g_w1h[HID * IN_DIM];     // [N=2048, K=2048]
__device__ __half g_w2h[H2 * HID];         // [N=1024, K=2048]
__device__ __half g_wph[NHC * H2];         // [N=1280, K=1024]
__device__ __half g_h1h[BSZ * HID];
__device__ __half g_h2h[BSZ * H2];
__device__ float g_logits[BSZ * NHC];
__device__ float g_bpack[NHC];

// ===========================================================================
// Low-level helpers (family-agnostic sm_80+ ISA)
// ===========================================================================
__device__ __forceinline__ uint32_t cvta_s(const void* p) {
    uint32_t a;
    asm("{ .reg .u64 t; cvta.to.shared.u64 t, %1; cvt.u32.u64 %0, t; }" : "=r"(a) : "l"(p));
    return a;
}
#define CP16(d, s) asm volatile("cp.async.cg.shared.global [%0], [%1], 16;" :: "r"(d), "l"(s))
#define CP_COMMIT  asm volatile("cp.async.commit_group;")
#define CP_WAIT1   asm volatile("cp.async.wait_group 1;")
#define LDSM4(r0, r1, r2, r3, a) \
    asm volatile("ldmatrix.sync.aligned.m8n8.x4.shared.b16 {%0,%1,%2,%3}, [%4];" \
                 : "=r"(r0), "=r"(r1), "=r"(r2), "=r"(r3) : "r"(a))
#define MMA_F16(d, a, b) \
    asm volatile("mma.sync.aligned.m16n8k16.row.col.f32.f16.f16.f32 " \
                 "{%0,%1,%2,%3},{%4,%5,%6,%7},{%8,%9},{%0,%1,%2,%3};" \
                 : "+f"((d)[0]), "+f"((d)[1]), "+f"((d)[2]), "+f"((d)[3]) \
                 : "r"((a)[0]), "r"((a)[1]), "r"((a)[2]), "r"((a)[3]), \
                   "r"((b)[0]), "r"((b)[1]))

// ===========================================================================
// GEMM: D[M,N] = A[M,K] @ B[N,K]^T + bias; A,B fp16, fp32 accumulate.
// Output fp16 (SPLIT) or fp32 (!SPLIT). Optional relu.
// CTA 128x128, K-step 64 as two 32-wide subtiles, 256 thr (8 warps = 2Mx4N,
// warp tile 64x32), 3-stage cp.async pipeline, 2 CTAs/SM.
// Smem subtiles row-major [rows][32 halves] = 64B/row; 16B chunk c of row r
// stored at chunk (c ^ ((r>>1)&3)) -> conflict-free ldmatrix + cp.async.
// ===========================================================================
constexpr int BM = 128, BN = 128, BK = 64, STAGES = 3;
constexpr int TB1 = BM * 64;                   // 8 KB (one 32-wide subtile)
constexpr int SM_A0 = 0, SM_A1 = TB1, SM_B0 = 2 * TB1, SM_B1 = 3 * TB1;
constexpr int STB = 4 * TB1;                   // 32 KB per stage
constexpr int GEMM_SMEM = STAGES * STB;        // 96 KB

template <bool RELU, bool SPLIT>
__global__ __launch_bounds__(256, 2) void gemm_f16(
    const __half* __restrict__ Ah, const __half* __restrict__ Bh,
    const float* __restrict__ bias,
    __half* __restrict__ oh, float* __restrict__ of, int M, int N, int K)
{
    extern __shared__ char smem[];
    const uint32_t sb = cvta_s(smem);
    const int tid = threadIdx.x, lane = tid & 31, warp = tid >> 5;
    const int bm = blockIdx.y * BM, bn = blockIdx.x * BN;
    const int m0w = (warp >> 2) * 64, n0w = (warp & 3) * 32;

    // cp.async mapping: thread t -> 16B chunk (t&3) of rows (t>>2)+64h
    const int lr = tid >> 2, lc = tid & 3;

    auto load_stage = [&](int s, int kc) {    // kc counts 64-wide K chunks
        const uint32_t stb = sb + s * STB;
#pragma unroll
        for (int sub = 0; sub < 2; sub++) {
            const int kg = kc * BK + sub * 32 + lc * 8;
            const uint32_t sa = stb + (sub ? SM_A1 : SM_A0);
            const uint32_t sbb = stb + (sub ? SM_B1 : SM_B0);
#pragma unroll
            for (int h = 0; h < 2; h++) {
                const int r = lr + h * 64;
                const uint32_t sw = r * 64 + ((lc ^ ((r >> 1) & 3)) << 4);
                CP16(sa + sw,  Ah + (size_t)(bm + r) * K + kg);
                CP16(sbb + sw, Bh + (size_t)(bn + r) * K + kg);
            }
        }
    };

    float acc[4][4][4];
#pragma unroll
    for (int a = 0; a < 4; a++)
#pragma unroll
        for (int b = 0; b < 4; b++)
#pragma unroll
            for (int c = 0; c < 4; c++) acc[a][b][c] = 0.f;

    const int NS = K / BK;
    load_stage(0, 0); CP_COMMIT;
    load_stage(1, 1); CP_COMMIT;

    // ldmatrix lane geometry (validated rounds 3-6)
    const int rA = lane & 15;                         // row within 16-row mfrag
    const int hA = lane >> 4;                         // k half
    const int rB = (lane & 7) + ((lane >> 4) << 3);   // row within 16-row nfrag pair
    const int hB = (lane >> 3) & 1;                   // k half

    int s_cur = 0, s_load = 2;
    for (int i = 0; i < NS; i++) {
        CP_WAIT1;                         // stage i complete (i+1 may pend)
        __syncthreads();
        if (i + 2 < NS) load_stage(s_load, i + 2);   // slot read in iter i-1
        CP_COMMIT;
        if (++s_load == STAGES) s_load = 0;

        const uint32_t stb = sb + s_cur * STB;
        if (++s_cur == STAGES) s_cur = 0;
#pragma unroll
        for (int sub = 0; sub < 2; sub++) {
            const uint32_t sa = stb + (sub ? SM_A1 : SM_A0);
            const uint32_t sbb = stb + (sub ? SM_B1 : SM_B0);
#pragma unroll
            for (int ks = 0; ks < 2; ks++) {
                uint32_t ahf[4][4], bf[4][2];
#pragma unroll
                for (int mf = 0; mf < 4; mf++) {
                    const int r = m0w + mf * 16 + rA;
                    const uint32_t off = r * 64 + (((ks * 2 + hA) ^ ((r >> 1) & 3)) << 4);
                    LDSM4(ahf[mf][0], ahf[mf][1], ahf[mf][2], ahf[mf][3], sa + off);
                }
#pragma unroll
                for (int p = 0; p < 2; p++) {
                    const int r = n0w + p * 16 + rB;
                    const uint32_t off = r * 64 + (((ks * 2 + hB) ^ ((r >> 1) & 3)) << 4);
                    uint32_t q0, q1, q2, q3;
                    LDSM4(q0, q1, q2, q3, sbb + off);
                    bf[2 * p][0] = q0; bf[2 * p][1] = q1;
                    bf[2 * p + 1][0] = q2; bf[2 * p + 1][1] = q3;
                }
#pragma unroll
                for (int mf = 0; mf < 4; mf++)
#pragma unroll
                    for (int nf = 0; nf < 4; nf++) MMA_F16(acc[mf][nf], ahf[mf], bf[nf]);
            }
        }
    }

    // ---- epilogue: bias (+relu), fp16 or fp32 stores ----
#pragma unroll
    for (int mf = 0; mf < 4; mf++)
#pragma unroll
        for (int nf = 0; nf < 4; nf++) {
            const int col = bn + n0w + nf * 8 + (lane & 3) * 2;
            const float bx = __ldg(bias + col), by = __ldg(bias + col + 1);
#pragma unroll
            for (int h = 0; h < 2; h++) {
                const int row = bm + m0w + mf * 16 + (lane >> 2) + h * 8;
                float v0 = acc[mf][nf][2 * h]     + bx;
                float v1 = acc[mf][nf][2 * h + 1] + by;
                if (RELU) { v0 = fmaxf(v0, 0.f); v1 = fmaxf(v1, 0.f); }
                if (SPLIT) {
                    __half2 p;
                    p.x = __float2half_rn(v0); p.y = __float2half_rn(v1);
                    *(__half2*)(oh + (size_t)row * N + col) = p;
                } else {
                    *(float2*)(of + (size_t)row * N + col) = make_float2(v0, v1);
                }
            }
        }
}

// ===========================================================================
// Conversion kernels
// ===========================================================================
__global__ void cast_fp16(const float* __restrict__ in, __half* __restrict__ oh, int n)
{
    int i = (blockIdx.x * blockDim.x + threadIdx.x) * 4;
    if (i >= n) return;
    float4 v = *(const float4*)(in + i);
    __half2 a, b;
    a.x = __float2half_rn(v.x); a.y = __float2half_rn(v.y);
    b.x = __float2half_rn(v.z); b.y = __float2half_rn(v.w);
    *(__half2*)(oh + i) = a;
    *(__half2*)(oh + i + 2) = b;
}

// in: [R, C] fp32 -> out: [C, R] fp16  (weights -> [N rows, K cols])
__global__ void transpose_cast(const float* __restrict__ in, __half* __restrict__ oh,
                               int R, int C)
{
    __shared__ float t[32][33];
    const int c0 = blockIdx.x * 32, r0 = blockIdx.y * 32;
    const int tx = threadIdx.x, ty = threadIdx.y;
#pragma unroll
    for (int k = 0; k < 4; k++)
        t[ty + 8 * k][tx] = in[(size_t)(r0 + ty + 8 * k) * C + c0 + tx];
    __syncthreads();
#pragma unroll
    for (int k = 0; k < 4; k++)
        oh[(size_t)(c0 + ty + 8 * k) * R + r0 + tx] = __float2half_rn(t[tx][ty + 8 * k]);
}

// Pack head weights into [NHC=1280 rows (N), H2=1024 cols (K)] fp16 + bias.
__global__ void pack_heads_t(const float* __restrict__ wr, const float* __restrict__ br,
                             const float* __restrict__ wl, const float* __restrict__ bl)
{
    int idx = blockIdx.x * blockDim.x + threadIdx.x;
    if (idx < NHC * H2) {
        int c = idx / H2, h = idx % H2;
        float v;
        if (c < 1024) { int k = c >> 5, r = c & 31; v = wr[((size_t)k * H2 + h) * 32 + r]; }
        else { int cc = c - 1024; int k = cc >> 3, l = cc & 7; v = wl[((size_t)k * H2 + h) * 8 + l]; }
        g_wph[idx] = __float2half_rn(v);
    }
    if (idx < NHC) g_bpack[idx] = (idx < 1024) ? br[idx] : bl[idx - 1024];
}

// ===========================================================================
// Softmax per head + interleaved scatter
// ===========================================================================
__global__ __launch_bounds__(256) void softmax_scatter(
    const float* __restrict__ logits, float* __restrict__ out)
{
    const int b = blockIdx.x, tid = threadIdx.x;
    const float* row = logits + (size_t)b * NHC;
    float* orow = out + (size_t)b * NHC;
    const int lane = tid & 31, warp = tid >> 5;
#pragma unroll
    for (int it = 0; it < 4; it++) {
        int k = warp + it * 8;
        float v = row[k * 32 + lane];
        float m = v;
#pragma unroll
        for (int o = 16; o; o >>= 1) m = fmaxf(m, __shfl_xor_sync(0xffffffffu, m, o));
        float e = __expf(v - m);
        float s = e;
#pragma unroll
        for (int o = 16; o; o >>= 1) s += __shfl_xor_sync(0xffffffffu, s, o);
        orow[(k >> 1) * 80 + (k & 1) * 32 + lane] = e / s;
    }
    {
        int g = tid >> 3, l8 = tid & 7;
        float v = row[1024 + g * 8 + l8];
        float m = v;
#pragma unroll
        for (int o = 4; o; o >>= 1) m = fmaxf(m, __shfl_xor_sync(0xffffffffu, m, o));
        float e = __expf(v - m);
        float s = e;
#pragma unroll
        for (int o = 4; o; o >>= 1) s += __shfl_xor_sync(0xffffffffu, s, o);
        orow[(g >> 1) * 80 + 64 + (g & 1) * 8 + l8] = e / s;
    }
}

// ===========================================================================
// Host side
// ===========================================================================
extern "C" void kernel_launch(void* const* d_in, const int* in_sizes, int n_in,
                              void* d_out, int out_size)
{
    const float* x  = (const float*)d_in[0];
    const float* w1 = (const float*)d_in[1];
    const float* b1 = (const float*)d_in[2];
    const float* w2 = (const float*)d_in[3];
    const float* b2 = (const float*)d_in[4];
    const float* wr = (const float*)d_in[5];
    const float* br = (const float*)d_in[6];
    const float* wl = (const float*)d_in[7];
    const float* bl = (const float*)d_in[8];
    float* out = (float*)d_out;

    void *xh, *w1h, *w2h, *wph, *h1h, *h2h, *lg, *bp;
    cudaGetSymbolAddress(&xh, g_xh);
    cudaGetSymbolAddress(&w1h, g_w1h);
    cudaGetSymbolAddress(&w2h, g_w2h);
    cudaGetSymbolAddress(&wph, g_wph);
    cudaGetSymbolAddress(&h1h, g_h1h); cudaGetSymbolAddress(&h2h, g_h2h);
    cudaGetSymbolAddress(&lg, g_logits); cudaGetSymbolAddress(&bp, g_bpack);

    cudaFuncSetAttribute(gemm_f16<true, true>,
                         cudaFuncAttributeMaxDynamicSharedMemorySize, GEMM_SMEM);
    cudaFuncSetAttribute(gemm_f16<false, false>,
                         cudaFuncAttributeMaxDynamicSharedMemorySize, GEMM_SMEM);

    // conversions (ordered so the ncu-profiled launch slot lands on GEMM1)
    cast_fp16<<<(BSZ * IN_DIM / 4 + 255) / 256, 256>>>(x, (__half*)xh, BSZ * IN_DIM);
    transpose_cast<<<dim3(HID / 32, IN_DIM / 32), dim3(32, 8)>>>(w1, (__half*)w1h, IN_DIM, HID);
    transpose_cast<<<dim3(H2 / 32, HID / 32), dim3(32, 8)>>>(w2, (__half*)w2h, HID, H2);

    // GEMM1: h1 = relu(x@w1+b1)   [4096,2048] K=2048
    gemm_f16<true, true><<<dim3(HID / BN, BSZ / BM), 256, GEMM_SMEM>>>(
        (const __half*)xh, (const __half*)w1h, b1, (__half*)h1h, nullptr, BSZ, HID, IN_DIM);

    pack_heads_t<<<(NHC * H2 + 255) / 256, 256>>>(wr, br, wl, bl);

    // GEMM2: h2 = relu(h1@w2+b2)  [4096,1024] K=2048
    gemm_f16<true, true><<<dim3(H2 / BN, BSZ / BM), 256, GEMM_SMEM>>>(
        (const __half*)h1h, (const __half*)w2h, b2, (__half*)h2h, nullptr, BSZ, H2, HID);
    // GEMM3: logits = h2@Wpack+bpack  [4096,1280] K=1024
    gemm_f16<false, false><<<dim3(NHC / BN, BSZ / BM), 256, GEMM_SMEM>>>(
        (const __half*)h2h, (const __half*)wph, (const float*)bp,
        nullptr, (float*)lg, BSZ, NHC, H2);

    softmax_scatter<<<BSZ, 256>>>((const float*)lg, out);
}

// round 8
// speedup vs baseline: 6.1840x; 1.0307x over previous
#include <cuda_runtime.h>
#include <cuda_fp16.h>
#include <cstdint>

// ---------------------------------------------------------------------------
// Actor_22625887715353 — round 8: fp16 mma.sync GEMMs (2 CTAs/SM) + softmax
// FUSED into GEMM3's epilogue (warp tile 64x32 => one RSU head per warp /
// one LAY head per nf; softmax via shfl.xor(1,2) butterfly over the 4 lanes
// sharing lane>>2). Eliminates the logits buffer + softmax_scatter kernel.
//   h1 = relu(x@w1+b1); h2 = relu(h1@w2+b2);
//   out = softmax-per-head(h2@Wpack+bpack), interleaved [B,16,80].
// ---------------------------------------------------------------------------

constexpr int BSZ = 4096, IN_DIM = 2048, HID = 2048, H2 = 1024, NHC = 1280;

// ---- device scratch (no cudaMalloc allowed) ----
__device__ __half g_xh[BSZ * IN_DIM];
__device__ __half g_w1h[HID * IN_DIM];     // [N=2048, K=2048]
__device__ __half g_w2h[H2 * HID];         // [N=1024, K=2048]
__device__ __half g_wph[NHC * H2];         // [N=1280, K=1024]
__device__ __half g_h1h[BSZ * HID];
__device__ __half g_h2h[BSZ * H2];
__device__ float g_bpack[NHC];

// ===========================================================================
// Low-level helpers (family-agnostic sm_80+ ISA)
// ===========================================================================
__device__ __forceinline__ uint32_t cvta_s(const void* p) {
    uint32_t a;
    asm("{ .reg .u64 t; cvta.to.shared.u64 t, %1; cvt.u32.u64 %0, t; }" : "=r"(a) : "l"(p));
    return a;
}
#define CP16(d, s) asm volatile("cp.async.cg.shared.global [%0], [%1], 16;" :: "r"(d), "l"(s))
#define CP_COMMIT  asm volatile("cp.async.commit_group;")
#define CP_WAIT1   asm volatile("cp.async.wait_group 1;")
#define LDSM4(r0, r1, r2, r3, a) \
    asm volatile("ldmatrix.sync.aligned.m8n8.x4.shared.b16 {%0,%1,%2,%3}, [%4];" \
                 : "=r"(r0), "=r"(r1), "=r"(r2), "=r"(r3) : "r"(a))
#define MMA_F16(d, a, b) \
    asm volatile("mma.sync.aligned.m16n8k16.row.col.f32.f16.f16.f32 " \
                 "{%0,%1,%2,%3},{%4,%5,%6,%7},{%8,%9},{%0,%1,%2,%3};" \
                 : "+f"((d)[0]), "+f"((d)[1]), "+f"((d)[2]), "+f"((d)[3]) \
                 : "r"((a)[0]), "r"((a)[1]), "r"((a)[2]), "r"((a)[3]), \
                   "r"((b)[0]), "r"((b)[1]))

// ===========================================================================
// GEMM: D[M,N] = A[M,K] @ B[N,K]^T + bias; A,B fp16, fp32 accumulate.
// Epilogue: SMAX=0 -> optional relu, fp16 stores (hidden layers);
//           SMAX=1 -> per-head softmax + interleaved scatter to fp32 out.
// CTA 128x128, K-step 64 as two 32-wide subtiles, 256 thr (8 warps = 2Mx4N,
// warp tile 64x32), 3-stage cp.async pipeline, 2 CTAs/SM.
// Smem subtiles row-major [rows][32 halves] = 64B/row; 16B chunk c of row r
// stored at chunk (c ^ ((r>>1)&3)) -> conflict-free ldmatrix + cp.async.
// ===========================================================================
constexpr int BM = 128, BN = 128, BK = 64, STAGES = 3;
constexpr int TB1 = BM * 64;                   // 8 KB (one 32-wide subtile)
constexpr int SM_A0 = 0, SM_A1 = TB1, SM_B0 = 2 * TB1, SM_B1 = 3 * TB1;
constexpr int STB = 4 * TB1;                   // 32 KB per stage
constexpr int GEMM_SMEM = STAGES * STB;        // 96 KB

template <bool RELU, bool SMAX>
__global__ __launch_bounds__(256, 2) void gemm_f16(
    const __half* __restrict__ Ah, const __half* __restrict__ Bh,
    const float* __restrict__ bias,
    __half* __restrict__ oh, float* __restrict__ of, int M, int N, int K)
{
    extern __shared__ char smem[];
    const uint32_t sb = cvta_s(smem);
    const int tid = threadIdx.x, lane = tid & 31, warp = tid >> 5;
    const int bm = blockIdx.y * BM, bn = blockIdx.x * BN;
    const int m0w = (warp >> 2) * 64, n0w = (warp & 3) * 32;

    // cp.async mapping: thread t -> 16B chunk (t&3) of rows (t>>2)+64h
    const int lr = tid >> 2, lc = tid & 3;

    auto load_stage = [&](int s, int kc) {    // kc counts 64-wide K chunks
        const uint32_t stb = sb + s * STB;
#pragma unroll
        for (int sub = 0; sub < 2; sub++) {
            const int kg = kc * BK + sub * 32 + lc * 8;
            const uint32_t sa = stb + (sub ? SM_A1 : SM_A0);
            const uint32_t sbb = stb + (sub ? SM_B1 : SM_B0);
#pragma unroll
            for (int h = 0; h < 2; h++) {
                const int r = lr + h * 64;
                const uint32_t sw = r * 64 + ((lc ^ ((r >> 1) & 3)) << 4);
                CP16(sa + sw,  Ah + (size_t)(bm + r) * K + kg);
                CP16(sbb + sw, Bh + (size_t)(bn + r) * K + kg);
            }
        }
    };

    float acc[4][4][4];
#pragma unroll
    for (int a = 0; a < 4; a++)
#pragma unroll
        for (int b = 0; b < 4; b++)
#pragma unroll
            for (int c = 0; c < 4; c++) acc[a][b][c] = 0.f;

    const int NS = K / BK;
    load_stage(0, 0); CP_COMMIT;
    load_stage(1, 1); CP_COMMIT;

    // ldmatrix lane geometry (validated rounds 3-7)
    const int rA = lane & 15;                         // row within 16-row mfrag
    const int hA = lane >> 4;                         // k half
    const int rB = (lane & 7) + ((lane >> 4) << 3);   // row within 16-row nfrag pair
    const int hB = (lane >> 3) & 1;                   // k half

    int s_cur = 0, s_load = 2;
    for (int i = 0; i < NS; i++) {
        CP_WAIT1;                         // stage i complete (i+1 may pend)
        __syncthreads();
        if (i + 2 < NS) load_stage(s_load, i + 2);   // slot read in iter i-1
        CP_COMMIT;
        if (++s_load == STAGES) s_load = 0;

        const uint32_t stb = sb + s_cur * STB;
        if (++s_cur == STAGES) s_cur = 0;
#pragma unroll
        for (int sub = 0; sub < 2; sub++) {
            const uint32_t sa = stb + (sub ? SM_A1 : SM_A0);
            const uint32_t sbb = stb + (sub ? SM_B1 : SM_B0);
#pragma unroll
            for (int ks = 0; ks < 2; ks++) {
                uint32_t ahf[4][4], bf[4][2];
#pragma unroll
                for (int mf = 0; mf < 4; mf++) {
                    const int r = m0w + mf * 16 + rA;
                    const uint32_t off = r * 64 + (((ks * 2 + hA) ^ ((r >> 1) & 3)) << 4);
                    LDSM4(ahf[mf][0], ahf[mf][1], ahf[mf][2], ahf[mf][3], sa + off);
                }
#pragma unroll
                for (int p = 0; p < 2; p++) {
                    const int r = n0w + p * 16 + rB;
                    const uint32_t off = r * 64 + (((ks * 2 + hB) ^ ((r >> 1) & 3)) << 4);
                    uint32_t q0, q1, q2, q3;
                    LDSM4(q0, q1, q2, q3, sbb + off);
                    bf[2 * p][0] = q0; bf[2 * p][1] = q1;
                    bf[2 * p + 1][0] = q2; bf[2 * p + 1][1] = q3;
                }
#pragma unroll
                for (int mf = 0; mf < 4; mf++)
#pragma unroll
                    for (int nf = 0; nf < 4; nf++) MMA_F16(acc[mf][nf], ahf[mf], bf[nf]);
            }
        }
    }

    if (!SMAX) {
        // ---- epilogue: bias (+relu), fp16 stores ----
#pragma unroll
        for (int mf = 0; mf < 4; mf++)
#pragma unroll
            for (int nf = 0; nf < 4; nf++) {
                const int col = bn + n0w + nf * 8 + (lane & 3) * 2;
                const float bx = __ldg(bias + col), by = __ldg(bias + col + 1);
#pragma unroll
                for (int h = 0; h < 2; h++) {
                    const int row = bm + m0w + mf * 16 + (lane >> 2) + h * 8;
                    float v0 = acc[mf][nf][2 * h]     + bx;
                    float v1 = acc[mf][nf][2 * h + 1] + by;
                    if (RELU) { v0 = fmaxf(v0, 0.f); v1 = fmaxf(v1, 0.f); }
                    __half2 p;
                    p.x = __float2half_rn(v0); p.y = __float2half_rn(v1);
                    *(__half2*)(oh + (size_t)row * N + col) = p;
                }
            }
    } else {
        // ---- epilogue: bias + per-head softmax + interleaved scatter ----
        // Warp N-extent (32 cols) = one RSU head; each nf (8 cols) = one LAY
        // head. A head-row's values live in the 4 lanes sharing lane>>2;
        // reduce with shfl.xor offsets 1,2 (stays within the 4-lane group).
        const int nbase = bn + n0w;            // warp-uniform
#pragma unroll
        for (int mf = 0; mf < 4; mf++)
#pragma unroll
            for (int h = 0; h < 2; h++) {
                const int row = bm + m0w + mf * 16 + (lane >> 2) + h * 8;
                float* orow = of + (size_t)row * NHC;
                float v[8];
#pragma unroll
                for (int nf = 0; nf < 4; nf++) {
                    const int col = nbase + nf * 8 + (lane & 3) * 2;
                    v[2 * nf]     = acc[mf][nf][2 * h]     + __ldg(bias + col);
                    v[2 * nf + 1] = acc[mf][nf][2 * h + 1] + __ldg(bias + col + 1);
                }
                if (nbase < 1024) {
                    // RSU head (width 32): k = nbase/32
                    float m = v[0];
#pragma unroll
                    for (int j = 1; j < 8; j++) m = fmaxf(m, v[j]);
                    m = fmaxf(m, __shfl_xor_sync(0xffffffffu, m, 1));
                    m = fmaxf(m, __shfl_xor_sync(0xffffffffu, m, 2));
                    float s = 0.f;
#pragma unroll
                    for (int j = 0; j < 8; j++) { v[j] = __expf(v[j] - m); s += v[j]; }
                    s += __shfl_xor_sync(0xffffffffu, s, 1);
                    s += __shfl_xor_sync(0xffffffffu, s, 2);
                    const float inv = 1.f / s;
                    const int k = nbase >> 5;
                    const int ob = (k >> 1) * 80 + (k & 1) * 32 + (lane & 3) * 2;
#pragma unroll
                    for (int nf = 0; nf < 4; nf++)
                        *(float2*)(orow + ob + nf * 8) =
                            make_float2(v[2 * nf] * inv, v[2 * nf + 1] * inv);
                } else {
                    // LAY heads (width 8): one head per nf
#pragma unroll
                    for (int nf = 0; nf < 4; nf++) {
                        float a0 = v[2 * nf], a1 = v[2 * nf + 1];
                        float m = fmaxf(a0, a1);
                        m = fmaxf(m, __shfl_xor_sync(0xffffffffu, m, 1));
                        m = fmaxf(m, __shfl_xor_sync(0xffffffffu, m, 2));
                        const float e0 = __expf(a0 - m), e1 = __expf(a1 - m);
                        float s = e0 + e1;
                        s += __shfl_xor_sync(0xffffffffu, s, 1);
                        s += __shfl_xor_sync(0xffffffffu, s, 2);
                        const float inv = 1.f / s;
                        const int k = (nbase + nf * 8 - 1024) >> 3;
                        const int ob = (k >> 1) * 80 + 64 + (k & 1) * 8 + (lane & 3) * 2;
                        *(float2*)(orow + ob) = make_float2(e0 * inv, e1 * inv);
                    }
                }
            }
    }
}

// ===========================================================================
// Conversion kernels
// ===========================================================================
__global__ void cast_fp16(const float* __restrict__ in, __half* __restrict__ oh, int n)
{
    int i = (blockIdx.x * blockDim.x + threadIdx.x) * 4;
    if (i >= n) return;
    float4 v = *(const float4*)(in + i);
    __half2 a, b;
    a.x = __float2half_rn(v.x); a.y = __float2half_rn(v.y);
    b.x = __float2half_rn(v.z); b.y = __float2half_rn(v.w);
    *(__half2*)(oh + i) = a;
    *(__half2*)(oh + i + 2) = b;
}

// in: [R, C] fp32 -> out: [C, R] fp16  (weights -> [N rows, K cols])
__global__ void transpose_cast(const float* __restrict__ in, __half* __restrict__ oh,
                               int R, int C)
{
    __shared__ float t[32][33];
    const int c0 = blockIdx.x * 32, r0 = blockIdx.y * 32;
    const int tx = threadIdx.x, ty = threadIdx.y;
#pragma unroll
    for (int k = 0; k < 4; k++)
        t[ty + 8 * k][tx] = in[(size_t)(r0 + ty + 8 * k) * C + c0 + tx];
    __syncthreads();
#pragma unroll
    for (int k = 0; k < 4; k++)
        oh[(size_t)(c0 + ty + 8 * k) * R + r0 + tx] = __float2half_rn(t[tx][ty + 8 * k]);
}

// Pack head weights into [NHC=1280 rows (N), H2=1024 cols (K)] fp16 + bias.
__global__ void pack_heads_t(const float* __restrict__ wr, const float* __restrict__ br,
                             const float* __restrict__ wl, const float* __restrict__ bl)
{
    int idx = blockIdx.x * blockDim.x + threadIdx.x;
    if (idx < NHC * H2) {
        int c = idx / H2, h = idx % H2;
        float v;
        if (c < 1024) { int k = c >> 5, r = c & 31; v = wr[((size_t)k * H2 + h) * 32 + r]; }
        else { int cc = c - 1024; int k = cc >> 3, l = cc & 7; v = wl[((size_t)k * H2 + h) * 8 + l]; }
        g_wph[idx] = __float2half_rn(v);
    }
    if (idx < NHC) g_bpack[idx] = (idx < 1024) ? br[idx] : bl[idx - 1024];
}

// ===========================================================================
// Host side
// ===========================================================================
extern "C" void kernel_launch(void* const* d_in, const int* in_sizes, int n_in,
                              void* d_out, int out_size)
{
    const float* x  = (const float*)d_in[0];
    const float* w1 = (const float*)d_in[1];
    const float* b1 = (const float*)d_in[2];
    const float* w2 = (const float*)d_in[3];
    const float* b2 = (const float*)d_in[4];
    const float* wr = (const float*)d_in[5];
    const float* br = (const float*)d_in[6];
    const float* wl = (const float*)d_in[7];
    const float* bl = (const float*)d_in[8];
    float* out = (float*)d_out;

    void *xh, *w1h, *w2h, *wph, *h1h, *h2h, *bp;
    cudaGetSymbolAddress(&xh, g_xh);
    cudaGetSymbolAddress(&w1h, g_w1h);
    cudaGetSymbolAddress(&w2h, g_w2h);
    cudaGetSymbolAddress(&wph, g_wph);
    cudaGetSymbolAddress(&h1h, g_h1h); cudaGetSymbolAddress(&h2h, g_h2h);
    cudaGetSymbolAddress(&bp, g_bpack);

    cudaFuncSetAttribute(gemm_f16<true, false>,
                         cudaFuncAttributeMaxDynamicSharedMemorySize, GEMM_SMEM);
    cudaFuncSetAttribute(gemm_f16<false, true>,
                         cudaFuncAttributeMaxDynamicSharedMemorySize, GEMM_SMEM);

    // conversions (ordered so the ncu-profiled launch slot lands on GEMM1)
    cast_fp16<<<(BSZ * IN_DIM / 4 + 255) / 256, 256>>>(x, (__half*)xh, BSZ * IN_DIM);
    transpose_cast<<<dim3(HID / 32, IN_DIM / 32), dim3(32, 8)>>>(w1, (__half*)w1h, IN_DIM, HID);
    transpose_cast<<<dim3(H2 / 32, HID / 32), dim3(32, 8)>>>(w2, (__half*)w2h, HID, H2);

    // GEMM1: h1 = relu(x@w1+b1)   [4096,2048] K=2048
    gemm_f16<true, false><<<dim3(HID / BN, BSZ / BM), 256, GEMM_SMEM>>>(
        (const __half*)xh, (const __half*)w1h, b1, (__half*)h1h, nullptr, BSZ, HID, IN_DIM);

    pack_heads_t<<<(NHC * H2 + 255) / 256, 256>>>(wr, br, wl, bl);

    // GEMM2: h2 = relu(h1@w2+b2)  [4096,1024] K=2048
    gemm_f16<true, false><<<dim3(H2 / BN, BSZ / BM), 256, GEMM_SMEM>>>(
        (const __half*)h1h, (const __half*)w2h, b2, (__half*)h2h, nullptr, BSZ, H2, HID);

    // GEMM3 + fused softmax/scatter: out = softmax(h2@Wpack+bpack)  K=1024
    gemm_f16<false, true><<<dim3(NHC / BN, BSZ / BM), 256, GEMM_SMEM>>>(
        (const __half*)h2h, (const __half*)wph, (const float*)bp,
        nullptr, out, BSZ, NHC, H2);
}

// round 9
// speedup vs baseline: 6.4205x; 1.0383x over previous
#include <cuda_runtime.h>
#include <cuda_fp16.h>
#include <cstdint>

// ---------------------------------------------------------------------------
// Actor_22625887715353 — round 9: round-8 GEMMs (fp16 mma.sync, 2 CTAs/SM,
// softmax fused into GEMM3) + ALL input conversions fused into ONE coalesced
// prep kernel (cast x, transpose w1/w2, smem-transpose head packing, bias).
// Fixes pack_heads_t's 32x read amplification (9.6us -> ~2us) and removes
// 3 kernel-launch gaps.
// ---------------------------------------------------------------------------

constexpr int BSZ = 4096, IN_DIM = 2048, HID = 2048, H2 = 1024, NHC = 1280;

// ---- device scratch (no cudaMalloc allowed) ----
__device__ __half g_xh[BSZ * IN_DIM];
__device__ __half g_w1h[HID * IN_DIM];     // [N=2048, K=2048]
__device__ __half g_w2h[H2 * HID];         // [N=1024, K=2048]
__device__ __half g_wph[NHC * H2];         // [N=1280, K=1024]
__device__ __half g_h1h[BSZ * HID];
__device__ __half g_h2h[BSZ * H2];
__device__ float g_bpack[NHC];

// ===========================================================================
// Low-level helpers (family-agnostic sm_80+ ISA)
// ===========================================================================
__device__ __forceinline__ uint32_t cvta_s(const void* p) {
    uint32_t a;
    asm("{ .reg .u64 t; cvta.to.shared.u64 t, %1; cvt.u32.u64 %0, t; }" : "=r"(a) : "l"(p));
    return a;
}
#define CP16(d, s) asm volatile("cp.async.cg.shared.global [%0], [%1], 16;" :: "r"(d), "l"(s))
#define CP_COMMIT  asm volatile("cp.async.commit_group;")
#define CP_WAIT1   asm volatile("cp.async.wait_group 1;")
#define LDSM4(r0, r1, r2, r3, a) \
    asm volatile("ldmatrix.sync.aligned.m8n8.x4.shared.b16 {%0,%1,%2,%3}, [%4];" \
                 : "=r"(r0), "=r"(r1), "=r"(r2), "=r"(r3) : "r"(a))
#define MMA_F16(d, a, b) \
    asm volatile("mma.sync.aligned.m16n8k16.row.col.f32.f16.f16.f32 " \
                 "{%0,%1,%2,%3},{%4,%5,%6,%7},{%8,%9},{%0,%1,%2,%3};" \
                 : "+f"((d)[0]), "+f"((d)[1]), "+f"((d)[2]), "+f"((d)[3]) \
                 : "r"((a)[0]), "r"((a)[1]), "r"((a)[2]), "r"((a)[3]), \
                   "r"((b)[0]), "r"((b)[1]))

// ===========================================================================
// GEMM (unchanged from round 8): D[M,N] = A[M,K] @ B[N,K]^T + bias.
// SMAX=0 -> relu + fp16 stores; SMAX=1 -> per-head softmax + scatter.
// CTA 128x128x64, 8 warps (2Mx4N, warp tile 64x32), 3-stage cp.async,
// 2 CTAs/SM.
// ===========================================================================
constexpr int BM = 128, BN = 128, BK = 64, STAGES = 3;
constexpr int TB1 = BM * 64;                   // 8 KB (one 32-wide subtile)
constexpr int SM_A0 = 0, SM_A1 = TB1, SM_B0 = 2 * TB1, SM_B1 = 3 * TB1;
constexpr int STB = 4 * TB1;                   // 32 KB per stage
constexpr int GEMM_SMEM = STAGES * STB;        // 96 KB

template <bool RELU, bool SMAX>
__global__ __launch_bounds__(256, 2) void gemm_f16(
    const __half* __restrict__ Ah, const __half* __restrict__ Bh,
    const float* __restrict__ bias,
    __half* __restrict__ oh, float* __restrict__ of, int M, int N, int K)
{
    extern __shared__ char smem[];
    const uint32_t sb = cvta_s(smem);
    const int tid = threadIdx.x, lane = tid & 31, warp = tid >> 5;
    const int bm = blockIdx.y * BM, bn = blockIdx.x * BN;
    const int m0w = (warp >> 2) * 64, n0w = (warp & 3) * 32;

    const int lr = tid >> 2, lc = tid & 3;

    auto load_stage = [&](int s, int kc) {
        const uint32_t stb = sb + s * STB;
#pragma unroll
        for (int sub = 0; sub < 2; sub++) {
            const int kg = kc * BK + sub * 32 + lc * 8;
            const uint32_t sa = stb + (sub ? SM_A1 : SM_A0);
            const uint32_t sbb = stb + (sub ? SM_B1 : SM_B0);
#pragma unroll
            for (int h = 0; h < 2; h++) {
                const int r = lr + h * 64;
                const uint32_t sw = r * 64 + ((lc ^ ((r >> 1) & 3)) << 4);
                CP16(sa + sw,  Ah + (size_t)(bm + r) * K + kg);
                CP16(sbb + sw, Bh + (size_t)(bn + r) * K + kg);
            }
        }
    };

    float acc[4][4][4];
#pragma unroll
    for (int a = 0; a < 4; a++)
#pragma unroll
        for (int b = 0; b < 4; b++)
#pragma unroll
            for (int c = 0; c < 4; c++) acc[a][b][c] = 0.f;

    const int NS = K / BK;
    load_stage(0, 0); CP_COMMIT;
    load_stage(1, 1); CP_COMMIT;

    const int rA = lane & 15;
    const int hA = lane >> 4;
    const int rB = (lane & 7) + ((lane >> 4) << 3);
    const int hB = (lane >> 3) & 1;

    int s_cur = 0, s_load = 2;
    for (int i = 0; i < NS; i++) {
        CP_WAIT1;
        __syncthreads();
        if (i + 2 < NS) load_stage(s_load, i + 2);
        CP_COMMIT;
        if (++s_load == STAGES) s_load = 0;

        const uint32_t stb = sb + s_cur * STB;
        if (++s_cur == STAGES) s_cur = 0;
#pragma unroll
        for (int sub = 0; sub < 2; sub++) {
            const uint32_t sa = stb + (sub ? SM_A1 : SM_A0);
            const uint32_t sbb = stb + (sub ? SM_B1 : SM_B0);
#pragma unroll
            for (int ks = 0; ks < 2; ks++) {
                uint32_t ahf[4][4], bf[4][2];
#pragma unroll
                for (int mf = 0; mf < 4; mf++) {
                    const int r = m0w + mf * 16 + rA;
                    const uint32_t off = r * 64 + (((ks * 2 + hA) ^ ((r >> 1) & 3)) << 4);
                    LDSM4(ahf[mf][0], ahf[mf][1], ahf[mf][2], ahf[mf][3], sa + off);
                }
#pragma unroll
                for (int p = 0; p < 2; p++) {
                    const int r = n0w + p * 16 + rB;
                    const uint32_t off = r * 64 + (((ks * 2 + hB) ^ ((r >> 1) & 3)) << 4);
                    uint32_t q0, q1, q2, q3;
                    LDSM4(q0, q1, q2, q3, sbb + off);
                    bf[2 * p][0] = q0; bf[2 * p][1] = q1;
                    bf[2 * p + 1][0] = q2; bf[2 * p + 1][1] = q3;
                }
#pragma unroll
                for (int mf = 0; mf < 4; mf++)
#pragma unroll
                    for (int nf = 0; nf < 4; nf++) MMA_F16(acc[mf][nf], ahf[mf], bf[nf]);
            }
        }
    }

    if (!SMAX) {
#pragma unroll
        for (int mf = 0; mf < 4; mf++)
#pragma unroll
            for (int nf = 0; nf < 4; nf++) {
                const int col = bn + n0w + nf * 8 + (lane & 3) * 2;
                const float bx = __ldg(bias + col), by = __ldg(bias + col + 1);
#pragma unroll
                for (int h = 0; h < 2; h++) {
                    const int row = bm + m0w + mf * 16 + (lane >> 2) + h * 8;
                    float v0 = acc[mf][nf][2 * h]     + bx;
                    float v1 = acc[mf][nf][2 * h + 1] + by;
                    if (RELU) { v0 = fmaxf(v0, 0.f); v1 = fmaxf(v1, 0.f); }
                    __half2 p;
                    p.x = __float2half_rn(v0); p.y = __float2half_rn(v1);
                    *(__half2*)(oh + (size_t)row * N + col) = p;
                }
            }
    } else {
        const int nbase = bn + n0w;            // warp-uniform
#pragma unroll
        for (int mf = 0; mf < 4; mf++)
#pragma unroll
            for (int h = 0; h < 2; h++) {
                const int row = bm + m0w + mf * 16 + (lane >> 2) + h * 8;
                float* orow = of + (size_t)row * NHC;
                float v[8];
#pragma unroll
                for (int nf = 0; nf < 4; nf++) {
                    const int col = nbase + nf * 8 + (lane & 3) * 2;
                    v[2 * nf]     = acc[mf][nf][2 * h]     + __ldg(bias + col);
                    v[2 * nf + 1] = acc[mf][nf][2 * h + 1] + __ldg(bias + col + 1);
                }
                if (nbase < 1024) {
                    float m = v[0];
#pragma unroll
                    for (int j = 1; j < 8; j++) m = fmaxf(m, v[j]);
                    m = fmaxf(m, __shfl_xor_sync(0xffffffffu, m, 1));
                    m = fmaxf(m, __shfl_xor_sync(0xffffffffu, m, 2));
                    float s = 0.f;
#pragma unroll
                    for (int j = 0; j < 8; j++) { v[j] = __expf(v[j] - m); s += v[j]; }
                    s += __shfl_xor_sync(0xffffffffu, s, 1);
                    s += __shfl_xor_sync(0xffffffffu, s, 2);
                    const float inv = 1.f / s;
                    const int k = nbase >> 5;
                    const int ob = (k >> 1) * 80 + (k & 1) * 32 + (lane & 3) * 2;
#pragma unroll
                    for (int nf = 0; nf < 4; nf++)
                        *(float2*)(orow + ob + nf * 8) =
                            make_float2(v[2 * nf] * inv, v[2 * nf + 1] * inv);
                } else {
#pragma unroll
                    for (int nf = 0; nf < 4; nf++) {
                        float a0 = v[2 * nf], a1 = v[2 * nf + 1];
                        float m = fmaxf(a0, a1);
                        m = fmaxf(m, __shfl_xor_sync(0xffffffffu, m, 1));
                        m = fmaxf(m, __shfl_xor_sync(0xffffffffu, m, 2));
                        const float e0 = __expf(a0 - m), e1 = __expf(a1 - m);
                        float s = e0 + e1;
                        s += __shfl_xor_sync(0xffffffffu, s, 1);
                        s += __shfl_xor_sync(0xffffffffu, s, 2);
                        const float inv = 1.f / s;
                        const int k = (nbase + nf * 8 - 1024) >> 3;
                        const int ob = (k >> 1) * 80 + 64 + (k & 1) * 8 + (lane & 3) * 2;
                        *(float2*)(orow + ob) = make_float2(e0 * inv, e1 * inv);
                    }
                }
            }
    }
}

// ===========================================================================
// Fused prep kernel: one launch, block ranges:
//  [0, PB0)            cast x -> fp16                 (4 elems/thread)
//  [PB0, PB1)          transpose w1 [2048,2048] -> [N,K] fp16
//  [PB1, PB2)          transpose w2 [2048,1024] -> [N,K] fp16
//  [PB2, PB3)          RSU heads: per (head k, 32-h tile) 32x32 transpose
//  [PB3, PB4)          LAY heads: per (head k, 32-h tile) 32x8 transpose
//  [PB4, PB5)          bias pack
// All reads and writes coalesced (smem tile transposes).
// ===========================================================================
constexpr int PB0 = (BSZ * IN_DIM / 4) / 256;              // 8192
constexpr int PB1 = PB0 + (HID / 32) * (IN_DIM / 32);      // +4096
constexpr int PB2 = PB1 + (H2 / 32) * (HID / 32);          // +2048
constexpr int PB3 = PB2 + 32 * (H2 / 32);                  // +1024 (rsu)
constexpr int PB4 = PB3 + 32 * (H2 / 32);                  // +1024 (lay)
constexpr int PB5 = PB4 + (NHC + 255) / 256;               // +5

__global__ __launch_bounds__(256) void prep_all(
    const float* __restrict__ x,  const float* __restrict__ w1,
    const float* __restrict__ w2, const float* __restrict__ wr,
    const float* __restrict__ br, const float* __restrict__ wl,
    const float* __restrict__ bl)
{
    __shared__ float t[32][33];
    const int b = blockIdx.x, tid = threadIdx.x;
    const int tx = tid & 31, ty = tid >> 5;     // (32, 8)

    if (b < PB0) {                              // ---- cast x ----
        const int i = (b * 256 + tid) * 4;
        float4 v = *(const float4*)(x + i);
        __half2 a0, a1;
        a0.x = __float2half_rn(v.x); a0.y = __float2half_rn(v.y);
        a1.x = __float2half_rn(v.z); a1.y = __float2half_rn(v.w);
        *(__half2*)(g_xh + i) = a0;
        *(__half2*)(g_xh + i + 2) = a1;
    } else if (b < PB2) {                       // ---- transpose w1 / w2 ----
        const float* in; __half* oh; int R, C, b2;
        if (b < PB1) { in = w1; oh = g_w1h; R = IN_DIM; C = HID; b2 = b - PB0; }
        else         { in = w2; oh = g_w2h; R = HID;    C = H2;  b2 = b - PB1; }
        const int c0 = (b2 % (C / 32)) * 32, r0 = (b2 / (C / 32)) * 32;
#pragma unroll
        for (int k = 0; k < 4; k++)
            t[ty + 8 * k][tx] = in[(size_t)(r0 + ty + 8 * k) * C + c0 + tx];
        __syncthreads();
#pragma unroll
        for (int k = 0; k < 4; k++)
            oh[(size_t)(c0 + ty + 8 * k) * R + r0 + tx] =
                __float2half_rn(t[tx][ty + 8 * k]);
    } else if (b < PB3) {                       // ---- RSU heads ----
        const int b2 = b - PB2;
        const int kh = b2 >> 5, h0 = (b2 & 31) * 32;
        const float* wrk = wr + (size_t)kh * H2 * 32;
#pragma unroll
        for (int k = 0; k < 4; k++)             // t[h_local][r]
            t[ty + 8 * k][tx] = wrk[(size_t)(h0 + ty + 8 * k) * 32 + tx];
        __syncthreads();
#pragma unroll
        for (int k = 0; k < 4; k++) {           // out[(kh*32+r)*H2 + h]
            const int j = ty + 8 * k;           // r
            g_wph[(size_t)(kh * 32 + j) * H2 + h0 + tx] = __float2half_rn(t[tx][j]);
        }
    } else if (b < PB4) {                       // ---- LAY heads ----
        const int b2 = b - PB3;
        const int kh = b2 >> 5, h0 = (b2 & 31) * 32;
        // read 256 contiguous floats: wl[kh][(h0+i)*8 + l], i=tid/8, l=tid&7
        t[tid >> 3][tid & 7] = wl[(size_t)kh * H2 * 8 + h0 * 8 + tid];
        __syncthreads();
        // out[(1024 + kh*8 + l)*H2 + h], l = ty (0..7), h = h0+tx
        g_wph[(size_t)(1024 + kh * 8 + ty) * H2 + h0 + tx] =
            __float2half_rn(t[tx][ty]);
    } else {                                    // ---- bias pack ----
        const int idx = (b - PB4) * 256 + tid;
        if (idx < NHC) g_bpack[idx] = (idx < 1024) ? br[idx] : bl[idx - 1024];
    }
}

// ===========================================================================
// Host side
// ===========================================================================
extern "C" void kernel_launch(void* const* d_in, const int* in_sizes, int n_in,
                              void* d_out, int out_size)
{
    const float* x  = (const float*)d_in[0];
    const float* w1 = (const float*)d_in[1];
    const float* b1 = (const float*)d_in[2];
    const float* w2 = (const float*)d_in[3];
    const float* b2 = (const float*)d_in[4];
    const float* wr = (const float*)d_in[5];
    const float* br = (const float*)d_in[6];
    const float* wl = (const float*)d_in[7];
    const float* bl = (const float*)d_in[8];
    float* out = (float*)d_out;

    void *xh, *w1h, *w2h, *wph, *h1h, *h2h, *bp;
    cudaGetSymbolAddress(&xh, g_xh);
    cudaGetSymbolAddress(&w1h, g_w1h);
    cudaGetSymbolAddress(&w2h, g_w2h);
    cudaGetSymbolAddress(&wph, g_wph);
    cudaGetSymbolAddress(&h1h, g_h1h); cudaGetSymbolAddress(&h2h, g_h2h);
    cudaGetSymbolAddress(&bp, g_bpack);

    cudaFuncSetAttribute(gemm_f16<true, false>,
                         cudaFuncAttributeMaxDynamicSharedMemorySize, GEMM_SMEM);
    cudaFuncSetAttribute(gemm_f16<false, true>,
                         cudaFuncAttributeMaxDynamicSharedMemorySize, GEMM_SMEM);

    // all conversions in one launch
    prep_all<<<PB5, 256>>>(x, w1, w2, wr, br, wl, bl);

    // GEMM1: h1 = relu(x@w1+b1)   [4096,2048] K=2048
    gemm_f16<true, false><<<dim3(HID / BN, BSZ / BM), 256, GEMM_SMEM>>>(
        (const __half*)xh, (const __half*)w1h, b1, (__half*)h1h, nullptr, BSZ, HID, IN_DIM);

    // GEMM2: h2 = relu(h1@w2+b2)  [4096,1024] K=2048
    gemm_f16<true, false><<<dim3(H2 / BN, BSZ / BM), 256, GEMM_SMEM>>>(
        (const __half*)h1h, (const __half*)w2h, b2, (__half*)h2h, nullptr, BSZ, H2, HID);

    // GEMM3 + fused softmax/scatter: out = softmax(h2@Wpack+bpack)  K=1024
    gemm_f16<false, true><<<dim3(NHC / BN, BSZ / BM), 256, GEMM_SMEM>>>(
        (const __half*)h2h, (const __half*)wph, (const float*)bp,
        nullptr, out, BSZ, NHC, H2);
}

// round 11
// speedup vs baseline: 6.5209x; 1.0156x over previous
#include <cuda_runtime.h>
#include <cuda_fp16.h>
#include <cstdint>

// ---------------------------------------------------------------------------
// Actor_22625887715353 — round 11 (= round 10 resubmit after infra failure):
// ONE persistent fused kernel for all three GEMMs (296 resident CTAs, static
// round-robin tile list, strip-counter dependencies G1->G2->G3). Eliminates
// wave-quantization tails and 2 launch gaps. Mainloop identical to round 9:
// fp16 mma.sync, CTA 128x128x64, 8 warps (2Mx4N, 64x32), 3-stage cp.async,
// 2 CTAs/SM. Softmax+scatter fused in G3 epilogue.
// Deadlock audit: grid==296==148x2 all-resident (launch_bounds(256,2) caps
// regs at 128 -> 64K/SM exactly); per-CTA item order increasing; position-1
// items are all G1 (never block) so all G1 completes; G2 waits only cnt1,
// G3 only cnt2 -> acyclic. fence.sc.gpu + ld.acquire + cp.async.cg (L2).
// ---------------------------------------------------------------------------

constexpr int BSZ = 4096, IN_DIM = 2048, HID = 2048, H2 = 1024, NHC = 1280;

// ---- device scratch (no cudaMalloc allowed) ----
__device__ __half g_xh[BSZ * IN_DIM];
__device__ __half g_w1h[HID * IN_DIM];     // [N=2048, K=2048]
__device__ __half g_w2h[H2 * HID];         // [N=1024, K=2048]
__device__ __half g_wph[NHC * H2];         // [N=1280, K=1024]
__device__ __half g_h1h[BSZ * HID];
__device__ __half g_h2h[BSZ * H2];
__device__ float g_bpack[NHC];
__device__ int   g_cnt1[32], g_cnt2[32];   // h1 / h2 row-strip ready counters

// ===========================================================================
// Low-level helpers (family-agnostic sm_80+ ISA)
// ===========================================================================
__device__ __forceinline__ uint32_t cvta_s(const void* p) {
    uint32_t a;
    asm("{ .reg .u64 t; cvta.to.shared.u64 t, %1; cvt.u32.u64 %0, t; }" : "=r"(a) : "l"(p));
    return a;
}
__device__ __forceinline__ int ld_acq(const int* p) {
    int v;
    asm volatile("ld.acquire.gpu.global.b32 %0, [%1];" : "=r"(v) : "l"(p) : "memory");
    return v;
}
#define CP16(d, s) asm volatile("cp.async.cg.shared.global [%0], [%1], 16;" :: "r"(d), "l"(s))
#define CP_COMMIT  asm volatile("cp.async.commit_group;")
#define CP_WAIT1   asm volatile("cp.async.wait_group 1;")
#define LDSM4(r0, r1, r2, r3, a) \
    asm volatile("ldmatrix.sync.aligned.m8n8.x4.shared.b16 {%0,%1,%2,%3}, [%4];" \
                 : "=r"(r0), "=r"(r1), "=r"(r2), "=r"(r3) : "r"(a))
#define MMA_F16(d, a, b) \
    asm volatile("mma.sync.aligned.m16n8k16.row.col.f32.f16.f16.f32 " \
                 "{%0,%1,%2,%3},{%4,%5,%6,%7},{%8,%9},{%0,%1,%2,%3};" \
                 : "+f"((d)[0]), "+f"((d)[1]), "+f"((d)[2]), "+f"((d)[3]) \
                 : "r"((a)[0]), "r"((a)[1]), "r"((a)[2]), "r"((a)[3]), \
                   "r"((b)[0]), "r"((b)[1]))

// ===========================================================================
// Tile geometry (round 7-9): CTA 128x128x64, 3-stage cp.async, 96 KB smem.
// ===========================================================================
constexpr int BM = 128, BN = 128, BK = 64, STAGES = 3;
constexpr int TB1 = BM * 64;
constexpr int SM_A0 = 0, SM_A1 = TB1, SM_B0 = 2 * TB1, SM_B1 = 3 * TB1;
constexpr int STB = 4 * TB1;                   // 32 KB per stage
constexpr int GEMM_SMEM = STAGES * STB;        // 96 KB

constexpr int NWORK   = 296;                   // 148 SMs x 2 CTAs (all resident)
constexpr int NT_G1   = 512;                   // 32 strips x 16
constexpr int NT_G2   = 256;                   // 32 strips x 8
constexpr int NT_G3   = 320;                   // 32 strips x 10
constexpr int N_ITEMS = NT_G1 + NT_G2 + NT_G3; // 1088

__global__ __launch_bounds__(256, 2) void fused_gemms(
    const float* __restrict__ b1, const float* __restrict__ b2,
    float* __restrict__ out)
{
    extern __shared__ char smem[];
    const uint32_t sb = cvta_s(smem);
    const int tid = threadIdx.x, lane = tid & 31, warp = tid >> 5;
    const int m0w = (warp >> 2) * 64, n0w = (warp & 3) * 32;
    const int lr = tid >> 2, lc = tid & 3;

    // ldmatrix lane geometry (validated rounds 3-9)
    const int rA = lane & 15;
    const int hA = lane >> 4;
    const int rB = (lane & 7) + ((lane >> 4) << 3);
    const int hB = (lane >> 3) & 1;

    for (int item = blockIdx.x; item < N_ITEMS; item += NWORK) {
        // ---- decode work item ----
        int gemm, bm, bn, K;
        const __half *A, *B;
        if (item < NT_G1) {
            gemm = 0; bm = (item >> 4) * BM; bn = (item & 15) * BN;
            A = g_xh; B = g_w1h; K = IN_DIM;
        } else if (item < NT_G1 + NT_G2) {
            const int i = item - NT_G1;
            gemm = 1; bm = (i >> 3) * BM; bn = (i & 7) * BN;
            A = g_h1h; B = g_w2h; K = HID;
        } else {
            const int i = item - NT_G1 - NT_G2;
            gemm = 2; bm = (i / 10) * BM; bn = (i % 10) * BN;
            A = g_h2h; B = g_wph; K = H2;
        }

        // ---- dependency wait (strip counters) ----
        if (tid == 0) {
            if (gemm == 1) { while (ld_acq(&g_cnt1[bm >> 7]) < 16) __nanosleep(64); }
            else if (gemm == 2) { while (ld_acq(&g_cnt2[bm >> 7]) < 8) __nanosleep(64); }
        }
        __syncthreads();

        auto load_stage = [&](int s, int kc) {
            const uint32_t stb = sb + s * STB;
#pragma unroll
            for (int sub = 0; sub < 2; sub++) {
                const int kg = kc * BK + sub * 32 + lc * 8;
                const uint32_t sa = stb + (sub ? SM_A1 : SM_A0);
                const uint32_t sbb = stb + (sub ? SM_B1 : SM_B0);
#pragma unroll
                for (int h = 0; h < 2; h++) {
                    const int r = lr + h * 64;
                    const uint32_t sw = r * 64 + ((lc ^ ((r >> 1) & 3)) << 4);
                    CP16(sa + sw,  A + (size_t)(bm + r) * K + kg);
                    CP16(sbb + sw, B + (size_t)(bn + r) * K + kg);
                }
            }
        };

        float acc[4][4][4];
#pragma unroll
        for (int a = 0; a < 4; a++)
#pragma unroll
            for (int b = 0; b < 4; b++)
#pragma unroll
                for (int c = 0; c < 4; c++) acc[a][b][c] = 0.f;

        const int NS = K / BK;
        load_stage(0, 0); CP_COMMIT;
        load_stage(1, 1); CP_COMMIT;

        int s_cur = 0, s_load = 2;
        for (int i = 0; i < NS; i++) {
            CP_WAIT1;
            __syncthreads();
            if (i + 2 < NS) load_stage(s_load, i + 2);
            CP_COMMIT;
            if (++s_load == STAGES) s_load = 0;

            const uint32_t stb = sb + s_cur * STB;
            if (++s_cur == STAGES) s_cur = 0;
#pragma unroll
            for (int sub = 0; sub < 2; sub++) {
                const uint32_t sa = stb + (sub ? SM_A1 : SM_A0);
                const uint32_t sbb = stb + (sub ? SM_B1 : SM_B0);
#pragma unroll
                for (int ks = 0; ks < 2; ks++) {
                    uint32_t ahf[4][4], bf[4][2];
#pragma unroll
                    for (int mf = 0; mf < 4; mf++) {
                        const int r = m0w + mf * 16 + rA;
                        const uint32_t off = r * 64 + (((ks * 2 + hA) ^ ((r >> 1) & 3)) << 4);
                        LDSM4(ahf[mf][0], ahf[mf][1], ahf[mf][2], ahf[mf][3], sa + off);
                    }
#pragma unroll
                    for (int p = 0; p < 2; p++) {
                        const int r = n0w + p * 16 + rB;
                        const uint32_t off = r * 64 + (((ks * 2 + hB) ^ ((r >> 1) & 3)) << 4);
                        uint32_t q0, q1, q2, q3;
                        LDSM4(q0, q1, q2, q3, sbb + off);
                        bf[2 * p][0] = q0; bf[2 * p][1] = q1;
                        bf[2 * p + 1][0] = q2; bf[2 * p + 1][1] = q3;
                    }
#pragma unroll
                    for (int mf = 0; mf < 4; mf++)
#pragma unroll
                        for (int nf = 0; nf < 4; nf++) MMA_F16(acc[mf][nf], ahf[mf], bf[nf]);
                }
            }
        }

        // ---- epilogue ----
        if (gemm < 2) {
            const float* bias = gemm ? b2 : b1;
            __half* oh = gemm ? g_h2h : g_h1h;
            const int No = gemm ? H2 : HID;
#pragma unroll
            for (int mf = 0; mf < 4; mf++)
#pragma unroll
                for (int nf = 0; nf < 4; nf++) {
                    const int col = bn + n0w + nf * 8 + (lane & 3) * 2;
                    const float bx = __ldg(bias + col), by = __ldg(bias + col + 1);
#pragma unroll
                    for (int h = 0; h < 2; h++) {
                        const int row = bm + m0w + mf * 16 + (lane >> 2) + h * 8;
                        float v0 = fmaxf(acc[mf][nf][2 * h]     + bx, 0.f);
                        float v1 = fmaxf(acc[mf][nf][2 * h + 1] + by, 0.f);
                        __half2 p;
                        p.x = __float2half_rn(v0); p.y = __float2half_rn(v1);
                        *(__half2*)(oh + (size_t)row * No + col) = p;
                    }
                }
            // signal strip completion (release)
            __threadfence();
            __syncthreads();
            if (tid == 0) atomicAdd(gemm ? &g_cnt2[bm >> 7] : &g_cnt1[bm >> 7], 1);
        } else {
            // bias + per-head softmax + interleaved scatter (round-8 logic)
            const int nbase = bn + n0w;            // warp-uniform
#pragma unroll
            for (int mf = 0; mf < 4; mf++)
#pragma unroll
                for (int h = 0; h < 2; h++) {
                    const int row = bm + m0w + mf * 16 + (lane >> 2) + h * 8;
                    float* orow = out + (size_t)row * NHC;
                    float v[8];
#pragma unroll
                    for (int nf = 0; nf < 4; nf++) {
                        const int col = nbase + nf * 8 + (lane & 3) * 2;
                        v[2 * nf]     = acc[mf][nf][2 * h]     + __ldg(g_bpack + col);
                        v[2 * nf + 1] = acc[mf][nf][2 * h + 1] + __ldg(g_bpack + col + 1);
                    }
                    if (nbase < 1024) {            // RSU head (width 32)
                        float m = v[0];
#pragma unroll
                        for (int j = 1; j < 8; j++) m = fmaxf(m, v[j]);
                        m = fmaxf(m, __shfl_xor_sync(0xffffffffu, m, 1));
                        m = fmaxf(m, __shfl_xor_sync(0xffffffffu, m, 2));
                        float s = 0.f;
#pragma unroll
                        for (int j = 0; j < 8; j++) { v[j] = __expf(v[j] - m); s += v[j]; }
                        s += __shfl_xor_sync(0xffffffffu, s, 1);
                        s += __shfl_xor_sync(0xffffffffu, s, 2);
                        const float inv = 1.f / s;
                        const int k = nbase >> 5;
                        const int ob = (k >> 1) * 80 + (k & 1) * 32 + (lane & 3) * 2;
#pragma unroll
                        for (int nf = 0; nf < 4; nf++)
                            *(float2*)(orow + ob + nf * 8) =
                                make_float2(v[2 * nf] * inv, v[2 * nf + 1] * inv);
                    } else {                       // LAY heads (width 8)
#pragma unroll
                        for (int nf = 0; nf < 4; nf++) {
                            float a0 = v[2 * nf], a1 = v[2 * nf + 1];
                            float m = fmaxf(a0, a1);
                            m = fmaxf(m, __shfl_xor_sync(0xffffffffu, m, 1));
                            m = fmaxf(m, __shfl_xor_sync(0xffffffffu, m, 2));
                            const float e0 = __expf(a0 - m), e1 = __expf(a1 - m);
                            float s = e0 + e1;
                            s += __shfl_xor_sync(0xffffffffu, s, 1);
                            s += __shfl_xor_sync(0xffffffffu, s, 2);
                            const float inv = 1.f / s;
                            const int k = (nbase + nf * 8 - 1024) >> 3;
                            const int ob = (k >> 1) * 80 + 64 + (k & 1) * 8 + (lane & 3) * 2;
                            *(float2*)(orow + ob) = make_float2(e0 * inv, e1 * inv);
                        }
                    }
                }
            __syncthreads();   // protect smem before next item
        }
    }
}

// ===========================================================================
// Fused prep kernel (round 9) + strip-counter zeroing.
// ===========================================================================
constexpr int PB0 = (BSZ * IN_DIM / 4) / 256;              // 8192
constexpr int PB1 = PB0 + (HID / 32) * (IN_DIM / 32);      // +4096
constexpr int PB2 = PB1 + (H2 / 32) * (HID / 32);          // +2048
constexpr int PB3 = PB2 + 32 * (H2 / 32);                  // +1024 (rsu)
constexpr int PB4 = PB3 + 32 * (H2 / 32);                  // +1024 (lay)
constexpr int PB5 = PB4 + (NHC + 255) / 256;               // +5

__global__ __launch_bounds__(256) void prep_all(
    const float* __restrict__ x,  const float* __restrict__ w1,
    const float* __restrict__ w2, const float* __restrict__ wr,
    const float* __restrict__ br, const float* __restrict__ wl,
    const float* __restrict__ bl)
{
    __shared__ float t[32][33];
    const int b = blockIdx.x, tid = threadIdx.x;
    const int tx = tid & 31, ty = tid >> 5;     // (32, 8)

    if (b < PB0) {                              // ---- cast x ----
        const int i = (b * 256 + tid) * 4;
        float4 v = *(const float4*)(x + i);
        __half2 a0, a1;
        a0.x = __float2half_rn(v.x); a0.y = __float2half_rn(v.y);
        a1.x = __float2half_rn(v.z); a1.y = __float2half_rn(v.w);
        *(__half2*)(g_xh + i) = a0;
        *(__half2*)(g_xh + i + 2) = a1;
    } else if (b < PB2) {                       // ---- transpose w1 / w2 ----
        const float* in; __half* oh; int R, C, b2;
        if (b < PB1) { in = w1; oh = g_w1h; R = IN_DIM; C = HID; b2 = b - PB0; }
        else         { in = w2; oh = g_w2h; R = HID;    C = H2;  b2 = b - PB1; }
        const int c0 = (b2 % (C / 32)) * 32, r0 = (b2 / (C / 32)) * 32;
#pragma unroll
        for (int k = 0; k < 4; k++)
            t[ty + 8 * k][tx] = in[(size_t)(r0 + ty + 8 * k) * C + c0 + tx];
        __syncthreads();
#pragma unroll
        for (int k = 0; k < 4; k++)
            oh[(size_t)(c0 + ty + 8 * k) * R + r0 + tx] =
                __float2half_rn(t[tx][ty + 8 * k]);
    } else if (b < PB3) {                       // ---- RSU heads ----
        const int b2 = b - PB2;
        const int kh = b2 >> 5, h0 = (b2 & 31) * 32;
        const float* wrk = wr + (size_t)kh * H2 * 32;
#pragma unroll
        for (int k = 0; k < 4; k++)             // t[h_local][r]
            t[ty + 8 * k][tx] = wrk[(size_t)(h0 + ty + 8 * k) * 32 + tx];
        __syncthreads();
#pragma unroll
        for (int k = 0; k < 4; k++) {
            const int j = ty + 8 * k;           // r
            g_wph[(size_t)(kh * 32 + j) * H2 + h0 + tx] = __float2half_rn(t[tx][j]);
        }
    } else if (b < PB4) {                       // ---- LAY heads ----
        const int b2 = b - PB3;
        const int kh = b2 >> 5, h0 = (b2 & 31) * 32;
        t[tid >> 3][tid & 7] = wl[(size_t)kh * H2 * 8 + h0 * 8 + tid];
        __syncthreads();
        g_wph[(size_t)(1024 + kh * 8 + ty) * H2 + h0 + tx] =
            __float2half_rn(t[tx][ty]);
    } else {                                    // ---- bias pack + counters ----
        const int idx = (b - PB4) * 256 + tid;
        if (idx < NHC) g_bpack[idx] = (idx < 1024) ? br[idx] : bl[idx - 1024];
        if (b == PB4 && tid < 32) { g_cnt1[tid] = 0; g_cnt2[tid] = 0; }
    }
}

// ===========================================================================
// Host side
// ===========================================================================
extern "C" void kernel_launch(void* const* d_in, const int* in_sizes, int n_in,
                              void* d_out, int out_size)
{
    const float* x  = (const float*)d_in[0];
    const float* w1 = (const float*)d_in[1];
    const float* b1 = (const float*)d_in[2];
    const float* w2 = (const float*)d_in[3];
    const float* b2 = (const float*)d_in[4];
    const float* wr = (const float*)d_in[5];
    const float* br = (const float*)d_in[6];
    const float* wl = (const float*)d_in[7];
    const float* bl = (const float*)d_in[8];
    float* out = (float*)d_out;

    cudaFuncSetAttribute(fused_gemms,
                         cudaFuncAttributeMaxDynamicSharedMemorySize, GEMM_SMEM);

    // all conversions + counter reset in one launch
    prep_all<<<PB5, 256>>>(x, w1, w2, wr, br, wl, bl);

    // persistent fused GEMM1+GEMM2+GEMM3(+softmax) kernel
    fused_gemms<<<NWORK, 256, GEMM_SMEM>>>(b1, b2, out);
}